// round 11
// baseline (speedup 1.0000x reference)
#include <cuda_runtime.h>
#include <cuda_bf16.h>
#include <cstdint>
#include <cstddef>

#define NN   10000
#define NP   10048          // padding for the elementwise kernels (157*64)
#define NPG  10112          // padding for the GEMM/topk (79*128)
#define DD   128
#define NCAND 32

// ---------------- device scratch ----------------
__device__ float g_xn[(size_t)NPG*DD];              // normalized fp32
__device__ __nv_bfloat16 g_xh[(size_t)NPG*DD];      // bf16 of normalized
__device__ __nv_bfloat16 g_simh[(size_t)NPG*NPG];   // bf16 sim (202 MB)
__device__ int   g_cand[(size_t)NN*NCAND];
__device__ int   g_knn[(size_t)NN*16];
__device__ float g_coef[(size_t)96*NP];             // [j][NP] per branch
__device__ float g_hyper[(size_t)NN*5*DD];

__device__ __forceinline__ uint32_t kmax32(uint32_t a, uint32_t b){ return a>b?a:b; }

// ---------------- normalize rows -> fp32 + bf16 ----------------
__global__ __launch_bounds__(256) void k_norm(const float* __restrict__ feats){
    int w = threadIdx.x >> 5, lane = threadIdx.x & 31;
    int row = blockIdx.x*8 + w;
    if (row >= NPG) return;
    float4 v = make_float4(0.f,0.f,0.f,0.f);
    if (row < NN){
        v = *(const float4*)(feats + (size_t)row*DD + lane*4);
        float ss = v.x*v.x + v.y*v.y + v.z*v.z + v.w*v.w;
        #pragma unroll
        for (int o=16;o;o>>=1) ss += __shfl_xor_sync(0xffffffffu, ss, o);
        float inv = 1.0f / fmaxf(sqrtf(ss), 1e-12f);
        v.x*=inv; v.y*=inv; v.z*=inv; v.w*=inv;
    }
    *(float4*)(g_xn + (size_t)row*DD + lane*4) = v;
    __nv_bfloat16 hi[4] = { __float2bfloat16_rn(v.x), __float2bfloat16_rn(v.y),
                            __float2bfloat16_rn(v.z), __float2bfloat16_rn(v.w) };
    *(uint2*)(g_xh + (size_t)row*DD + lane*4) = *(uint2*)hi;
}

// ---------------- approx sim = xh @ xh^T (single-pass bf16 HMMA) ----------
#define LDSM4(r0,r1,r2,r3,addr) \
    asm volatile("ldmatrix.sync.aligned.m8n8.x4.shared.b16 {%0,%1,%2,%3},[%4];" \
        : "=r"(r0),"=r"(r1),"=r"(r2),"=r"(r3) : "r"(addr))
#define LDSM2(r0,r1,addr) \
    asm volatile("ldmatrix.sync.aligned.m8n8.x2.shared.b16 {%0,%1},[%2];" \
        : "=r"(r0),"=r"(r1) : "r"(addr))
#define MMA16816(c,a,b) \
    asm volatile("mma.sync.aligned.m16n8k16.row.col.f32.bf16.bf16.f32 " \
        "{%0,%1,%2,%3},{%4,%5,%6,%7},{%8,%9},{%0,%1,%2,%3};" \
        : "+f"(c[0]),"+f"(c[1]),"+f"(c[2]),"+f"(c[3]) \
        : "r"(a[0]),"r"(a[1]),"r"(a[2]),"r"(a[3]),"r"(b[0]),"r"(b[1]))

#define SROW2 136        // smem row stride in bf16 (272B) — conflict-free ldmatrix
#define SIM_SMEM (2*128*SROW2*2)   // 69632 bytes

__global__ __launch_bounds__(256) void k_simT(){
    extern __shared__ __align__(16) char smem[];
    char* sA = smem;
    char* sB = smem + 128*SROW2*2;

    const int tid  = threadIdx.x;
    const int wid  = tid >> 5;
    const int lane = tid & 31;
    const int bm = blockIdx.y, bn = blockIdx.x;
    const int warpM = (wid & 3) * 32;
    const int warpN = (wid >> 2) * 64;

    float c[2][8][4];
    #pragma unroll
    for (int t=0;t<2;t++)
        #pragma unroll
        for (int j=0;j<8;j++)
            #pragma unroll
            for (int q=0;q<4;q++) c[t][j][q] = 0.f;

    #pragma unroll
    for (int i=0;i<8;i++){
        int e = tid + i*256;
        int r = e >> 4, c8 = e & 15;
        size_t ga = (size_t)(bm*128 + r)*DD + c8*8;
        size_t gb = (size_t)(bn*128 + r)*DD + c8*8;
        *(uint4*)(sA + (r*SROW2 + c8*8)*2) = *(const uint4*)(g_xh + ga);
        *(uint4*)(sB + (r*SROW2 + c8*8)*2) = *(const uint4*)(g_xh + gb);
    }
    __syncthreads();

    uint32_t aoff = (uint32_t)((warpM + (lane & 15))*SROW2*2 + (lane >> 4)*16);
    uint32_t boff = (uint32_t)((warpN + (lane & 7))*SROW2*2 + ((lane >> 3) & 1)*16);
    uint32_t sA_u = (uint32_t)__cvta_generic_to_shared(sA);
    uint32_t sB_u = (uint32_t)__cvta_generic_to_shared(sB);

    #pragma unroll
    for (int ks=0; ks<8; ks++){
        uint32_t ah[2][4];
        #pragma unroll
        for (int t=0;t<2;t++){
            uint32_t ad = aoff + t*(16*SROW2*2) + ks*32;
            LDSM4(ah[t][0],ah[t][1],ah[t][2],ah[t][3], sA_u + ad);
        }
        #pragma unroll
        for (int j=0;j<8;j++){
            uint32_t bh[2];
            uint32_t bd = boff + j*(8*SROW2*2) + ks*32;
            LDSM2(bh[0],bh[1], sB_u + bd);
            #pragma unroll
            for (int t=0;t<2;t++)
                MMA16816(c[t][j], ah[t], bh);
        }
    }

    const int r0 = bm*128 + warpM + (lane >> 2);
    const int c0 = bn*128 + warpN + (lane & 3)*2;
    #pragma unroll
    for (int t=0;t<2;t++){
        #pragma unroll
        for (int j=0;j<8;j++){
            size_t base = (size_t)(r0 + t*16)*NPG + c0 + j*8;
            *(__nv_bfloat162*)(g_simh + base) =
                __float22bfloat162_rn(make_float2(c[t][j][0], c[t][j][1]));
            *(__nv_bfloat162*)(g_simh + base + 8ull*NPG) =
                __float22bfloat162_rn(make_float2(c[t][j][2], c[t][j][3]));
        }
    }
}

// ---------------- per-row top-32 candidates (bf16 keys, u32 selection) -----
__device__ __forceinline__ uint32_t bf16key(uint32_t u16, int j){
    uint32_t m = (u16 & 0x8000u) ? ((~u16) & 0xFFFFu) : (u16 | 0x8000u);
    return (m << 14) | (uint32_t)(16383 - j);
}

__global__ __launch_bounds__(128) void k_topk(){
    __shared__ uint32_t sk[16][128];
    __shared__ uint32_t wmax[4];
    int row = blockIdx.x;
    int tid = threadIdx.x;
    const uint4* srow4 = (const uint4*)(g_simh + (size_t)row*NPG);

    uint32_t t[16];
    #pragma unroll
    for (int r=0;r<16;r++) t[r]=0u;

    #pragma unroll 1
    for (int it=0; it<10; it++){
        int v4 = it*128 + tid;
        if (v4 >= 1250) break;          // 1250*8 == 10000 exactly
        uint4 q = srow4[v4];
        int jb = v4*8;
        uint32_t ws[4] = {q.x, q.y, q.z, q.w};
        #pragma unroll
        for (int wv=0; wv<4; wv++){
            uint32_t klo = bf16key(ws[wv] & 0xFFFFu, jb + wv*2);
            uint32_t khi = bf16key(ws[wv] >> 16,     jb + wv*2 + 1);
            if (klo > t[15]){
                t[15] = klo;
                #pragma unroll
                for (int r=15;r>0;r--)
                    if (t[r] > t[r-1]){ uint32_t tmp=t[r-1]; t[r-1]=t[r]; t[r]=tmp; }
            }
            if (khi > t[15]){
                t[15] = khi;
                #pragma unroll
                for (int r=15;r>0;r--)
                    if (t[r] > t[r-1]){ uint32_t tmp=t[r-1]; t[r-1]=t[r]; t[r]=tmp; }
            }
        }
    }
    #pragma unroll
    for (int r=0;r<16;r++) sk[r][tid] = t[r];
    uint32_t lmax = t[0];               // t sorted desc
    __syncthreads();

    for (int sel=0; sel<NCAND; sel++){
        uint32_t m = lmax;
        #pragma unroll
        for (int o=16;o;o>>=1) m = kmax32(m, __shfl_xor_sync(0xffffffffu, m, o));
        if ((tid & 31) == 0) wmax[tid >> 5] = m;
        __syncthreads();
        uint32_t best = kmax32(kmax32(wmax[0],wmax[1]), kmax32(wmax[2],wmax[3]));
        if (lmax == best){
            #pragma unroll
            for (int r=0;r<16;r++){
                if (sk[r][tid] == best){ sk[r][tid] = 0u; break; }
            }
            uint32_t nm = 0u;
            #pragma unroll
            for (int r=0;r<16;r++) nm = kmax32(nm, sk[r][tid]);
            lmax = nm;
        }
        if (tid == 0) g_cand[(size_t)row*NCAND + sel] = 16383 - (int)(best & 16383u);
        __syncthreads();
    }
}

// ---------------- fp32 re-rank of 32 candidates -> top-16 ----------------
__global__ __launch_bounds__(256) void k_refine(){
    int w = threadIdx.x >> 5, lane = threadIdx.x & 31;
    int row = blockIdx.x*8 + w;
    if (row >= NN) return;
    float4 xr = *(const float4*)(g_xn + (size_t)row*DD + lane*4);
    int myidx = g_cand[(size_t)row*NCAND + lane];
    unsigned long long mykey = 0ull;
    #pragma unroll 4
    for (int c=0; c<NCAND; c++){
        int cand = __shfl_sync(0xffffffffu, myidx, c);
        float4 xc = *(const float4*)(g_xn + (size_t)cand*DD + lane*4);
        float p = xr.x*xc.x + xr.y*xc.y + xr.z*xc.z + xr.w*xc.w;
        #pragma unroll
        for (int o=16;o;o>>=1) p += __shfl_xor_sync(0xffffffffu, p, o);
        if (lane == c){
            unsigned u = __float_as_uint(p);
            u = (u & 0x80000000u) ? ~u : (u | 0x80000000u);
            mykey = ((unsigned long long)u << 32) | (unsigned)(~(unsigned)myidx);
        }
    }
    int rank = 0;
    #pragma unroll
    for (int peer=0; peer<32; peer++){
        unsigned long long pk = __shfl_sync(0xffffffffu, mykey, peer);
        rank += (pk > mykey) ? 1 : 0;
    }
    if (rank < 16) g_knn[(size_t)row*16 + rank] = myidx;
}

// ---------------- fused VertexConv: logits + softmax + coef ----------------
// smem layout (floats): xsT[32][65]x4 (8320) | ws 16x128 (2048) | bKK K*K | ms 64x(K+1)
template<int K>
__device__ __forceinline__ void mc_body(const float* __restrict__ feats,
                                        const int* __restrict__ idx,
                                        int stride, int off0,
                                        const float* __restrict__ wKK,
                                        const float* __restrict__ bKK,
                                        const float* __restrict__ wK1,
                                        size_t coff){
    extern __shared__ float sm[];
    float4* xsT4 = (float4*)sm;                 // [32][65]
    float*  ws   = sm + 8320;                   // [16][128]
    float*  bks  = sm + 8320 + 2048;            // [K*K]
    float*  ms   = sm + 8320 + 2048 + K*K;      // [64][K+1]

    const int tid = threadIdx.x;
    const int n0 = blockIdx.x*64;
    const int n  = tid & 63;
    const int jg = tid >> 6;

    for (int e=tid; e<K*K; e+=256) bks[e] = bKK[e];

    float coef_r[K];
    #pragma unroll
    for (int j=0;j<K;j++) coef_r[j]=0.f;

    #pragma unroll 1
    for (int i=0;i<K;i++){
        __syncthreads();            // xsT/ws/ms free from previous iteration
        for (int e=tid; e<64*32; e+=256){
            int nn=e>>5, d4=e&31;
            int ng = n0+nn;
            int src = (ng<NN) ? idx[(size_t)ng*stride + off0 + i] : 0;
            xsT4[d4*65+nn] = *(const float4*)(feats + (size_t)src*DD + d4*4);
        }
        #pragma unroll
        for (int jc=0; jc<K/16; jc++){
            for (int e=tid; e<16*32; e+=256){
                int jl=e>>5, d4=e&31;
                *(float4*)&ws[jl*128+d4*4] =
                    *(const float4*)(wKK + ((size_t)(i*K + jc*16 + jl))*DD + d4*4);
            }
            __syncthreads();
            float acc[4]={0.f,0.f,0.f,0.f};
            #pragma unroll
            for (int d4=0; d4<32; d4++){
                float4 xv = xsT4[d4*65+n];
                #pragma unroll
                for (int jj=0; jj<4; jj++){
                    float4 w = *(float4*)&ws[(jg*4+jj)*128 + d4*4];
                    acc[jj] += xv.x*w.x + xv.y*w.y + xv.z*w.z + xv.w*w.w;
                }
            }
            #pragma unroll
            for (int jj=0; jj<4; jj++)
                ms[n*(K+1) + jc*16 + jg*4 + jj] = acc[jj];
            if (jc+1 < K/16) __syncthreads();
        }
        __syncthreads();            // ms complete
        if (tid < 64){
            float v[K]; float m = -1e30f;
            #pragma unroll
            for (int j=0;j<K;j++){ v[j] = ms[tid*(K+1)+j] + bks[i*K+j]; m = fmaxf(m, v[j]); }
            float s = 0.f;
            #pragma unroll
            for (int j=0;j<K;j++){ v[j] = __expf(v[j]-m); s += v[j]; }
            float p = wK1[i] / s;
            #pragma unroll
            for (int j=0;j<K;j++) coef_r[j] += p * v[j];
        }
    }
    __syncthreads();
    if (tid < 64){
        #pragma unroll
        for (int j=0;j<K;j++)
            g_coef[coff + (size_t)j*NP + n0 + tid] = coef_r[j];
    }
}

__global__ __launch_bounds__(256) void k_mc16(const float* __restrict__ feats,
                                              const int* __restrict__ cidx,
                                              const float* __restrict__ wKK_c,
                                              const float* __restrict__ bKK_c,
                                              const float* __restrict__ wK1_c,
                                              const float* __restrict__ wKK_n,
                                              const float* __restrict__ bKK_n,
                                              const float* __restrict__ wK1_n){
    int br = blockIdx.y;
    if (br < 3)
        mc_body<16>(feats, cidx, 48, br*16, wKK_c, bKK_c, wK1_c, (size_t)br*16*NP);
    else
        mc_body<16>(feats, g_knn, 16, 0, wKK_n, bKK_n, wK1_n, (size_t)48*NP);
}

__global__ __launch_bounds__(256) void k_mc32(const float* __restrict__ feats,
                                              const int* __restrict__ sidx,
                                              const float* __restrict__ wKK_s,
                                              const float* __restrict__ bKK_s,
                                              const float* __restrict__ wK1_s){
    mc_body<32>(feats, sidx, 32, 0, wKK_s, bKK_s, wK1_s, (size_t)64*NP);
}

#define MC16_SMEM ((8320 + 2048 + 16*16 + 64*17)*4)   // 46848 B
#define MC32_SMEM ((8320 + 2048 + 32*32 + 64*33)*4)   // 54016 B

// ---------------- hyper[n][t][:] = sum_j coef[j][n]*feats[idx(n,j)] + bK1 ---
__global__ __launch_bounds__(256) void k_hyper_all(const float* __restrict__ feats,
                                                   const int* __restrict__ cidx,
                                                   const int* __restrict__ sidx,
                                                   const float* __restrict__ bK1_c,
                                                   const float* __restrict__ bK1_n,
                                                   const float* __restrict__ bK1_s){
    int w = threadIdx.x >> 5, lane = threadIdx.x & 31;
    int n = blockIdx.x*8 + w;
    if (n >= NN) return;
    int t = blockIdx.y;
    const int* idx; int stride, off0, K; const float* bK1; size_t coff;
    if (t < 3){ idx = cidx; stride = 48; off0 = t*16; K = 16; bK1 = bK1_c; coff = (size_t)t*16*NP; }
    else if (t == 3){ idx = g_knn; stride = 16; off0 = 0; K = 16; bK1 = bK1_n; coff = (size_t)48*NP; }
    else { idx = sidx; stride = 32; off0 = 0; K = 32; bK1 = bK1_s; coff = (size_t)64*NP; }

    const float* coef = g_coef + coff;
    float4 acc = make_float4(0.f,0.f,0.f,0.f);
    #pragma unroll 4
    for (int j=0;j<K;j++){
        float c = __ldg(&coef[(size_t)j*NP + n]);
        int src = idx[(size_t)n*stride + off0 + j];
        float4 f = *(const float4*)(feats + (size_t)src*DD + lane*4);
        acc.x += c*f.x; acc.y += c*f.y; acc.z += c*f.z; acc.w += c*f.w;
    }
    float b = bK1[0];
    acc.x += b; acc.y += b; acc.z += b; acc.w += b;
    *(float4*)(g_hyper + ((size_t)n*5 + t)*DD + lane*4) = acc;
}

// ---------------- EdgeConv attention + final FC ----------------
__global__ __launch_bounds__(128) void k_final(const float* __restrict__ ec_w1,
                                               const float* __restrict__ ec_b1,
                                               const float* __restrict__ ec_w2,
                                               const float* __restrict__ ec_b2,
                                               const float* __restrict__ fc_w,
                                               const float* __restrict__ fc_b,
                                               float* __restrict__ out){
    extern __shared__ float fsm[];
    float* fcw  = fsm;
    float* w1s  = fsm + 16384;
    float* xs   = fsm + 16384 + 4096;
    float* aggs = xs + 4*640;
    int tid = threadIdx.x;
    for (int e=tid; e<16384/4; e+=128)
        *(float4*)&fcw[e*4] = *(const float4*)&fc_w[e*4];
    for (int e=tid; e<4096/4; e+=128)
        *(float4*)&w1s[e*4] = *(const float4*)&ec_w1[e*4];
    __syncthreads();

    int w = tid >> 5, lane = tid & 31;
    int n = blockIdx.x*4 + w;

    float4 xr[5];
    #pragma unroll
    for (int t=0;t<5;t++){
        xr[t] = *(const float4*)(g_hyper + ((size_t)n*5 + t)*DD + lane*4);
        *(float4*)&xs[w*640 + t*128 + lane*4] = xr[t];
    }
    __syncwarp();

    float w2v = ec_w2[lane];
    float b1v = ec_b1[lane];
    float sc[5];
    #pragma unroll
    for (int t=0;t<5;t++){
        float h = b1v;
        #pragma unroll 4
        for (int d=0; d<DD; d++)
            h += xs[w*640 + t*128 + d] * w1s[d*32 + lane];
        h = fmaxf(h, 0.f);
        float p = h * w2v;
        #pragma unroll
        for (int o=16;o;o>>=1) p += __shfl_xor_sync(0xffffffffu, p, o);
        sc[t] = p;
    }
    float b2 = ec_b2[0];
    float m = -1e30f;
    #pragma unroll
    for (int t=0;t<5;t++){ sc[t] += b2; m = fmaxf(m, sc[t]); }
    float s = 0.f;
    #pragma unroll
    for (int t=0;t<5;t++){ sc[t] = __expf(sc[t]-m); s += sc[t]; }
    float inv = 1.f/s;
    #pragma unroll
    for (int t=0;t<5;t++) sc[t] *= inv;

    float4 a = make_float4(0.f,0.f,0.f,0.f);
    #pragma unroll
    for (int t=0;t<5;t++){
        a.x += sc[t]*xr[t].x; a.y += sc[t]*xr[t].y;
        a.z += sc[t]*xr[t].z; a.w += sc[t]*xr[t].w;
    }
    *(float4*)&aggs[w*128 + lane*4] = a;
    __syncwarp();

    float4 o = *(const float4*)&fc_b[lane*4];
    #pragma unroll 4
    for (int d=0; d<DD; d++){
        float av = aggs[w*128 + d];
        float4 fw = *(const float4*)&fcw[d*128 + lane*4];
        o.x += av*fw.x; o.y += av*fw.y; o.z += av*fw.z; o.w += av*fw.w;
    }
    o.x = fmaxf(o.x,0.f); o.y = fmaxf(o.y,0.f);
    o.z = fmaxf(o.z,0.f); o.w = fmaxf(o.w,0.f);
    *(float4*)(out + (size_t)n*DD + lane*4) = o;
}

// ---------------- launch ----------------
extern "C" void kernel_launch(void* const* d_in, const int* in_sizes, int n_in,
                              void* d_out, int out_size){
    const float* feats  = (const float*)d_in[1];
    const int*   cidx   = (const int*)d_in[2];
    const int*   sidx   = (const int*)d_in[3];
    const float* wKK_c  = (const float*)d_in[5];
    const float* bKK_c  = (const float*)d_in[6];
    const float* wK1_c  = (const float*)d_in[7];
    const float* bK1_c  = (const float*)d_in[8];
    const float* wKK_n  = (const float*)d_in[9];
    const float* bKK_n  = (const float*)d_in[10];
    const float* wK1_n  = (const float*)d_in[11];
    const float* bK1_n  = (const float*)d_in[12];
    const float* wKK_s  = (const float*)d_in[13];
    const float* bKK_s  = (const float*)d_in[14];
    const float* wK1_s  = (const float*)d_in[15];
    const float* bK1_s  = (const float*)d_in[16];
    const float* ec_w1  = (const float*)d_in[17];
    const float* ec_b1  = (const float*)d_in[18];
    const float* ec_w2  = (const float*)d_in[19];
    const float* ec_b2  = (const float*)d_in[20];
    const float* fc_w   = (const float*)d_in[21];
    const float* fc_b   = (const float*)d_in[22];
    float* out = (float*)d_out;

    cudaFuncSetAttribute(k_simT, cudaFuncAttributeMaxDynamicSharedMemorySize, SIM_SMEM);
    cudaFuncSetAttribute(k_mc16, cudaFuncAttributeMaxDynamicSharedMemorySize, MC16_SMEM);
    cudaFuncSetAttribute(k_mc32, cudaFuncAttributeMaxDynamicSharedMemorySize, MC32_SMEM);
    cudaFuncSetAttribute(k_final, cudaFuncAttributeMaxDynamicSharedMemorySize, 94208);

    k_norm<<<NPG/8, 256>>>(feats);
    k_simT<<<dim3(NPG/128, NPG/128), 256, SIM_SMEM>>>();
    k_topk<<<NN, 128>>>();
    k_refine<<<(NN+7)/8, 256>>>();

    k_mc16<<<dim3(NP/64, 4), 256, MC16_SMEM>>>(feats, cidx, wKK_c, bKK_c, wK1_c,
                                               wKK_n, bKK_n, wK1_n);
    k_mc32<<<dim3(NP/64, 1), 256, MC32_SMEM>>>(feats, sidx, wKK_s, bKK_s, wK1_s);

    k_hyper_all<<<dim3(NN/8,5),256>>>(feats, cidx, sidx, bK1_c, bK1_n, bK1_s);

    k_final<<<NN/4, 128, 94208>>>(ec_w1, ec_b1, ec_w2, ec_b2, fc_w, fc_b, out);
}

// round 14
// speedup vs baseline: 1.1327x; 1.1327x over previous
#include <cuda_runtime.h>
#include <cuda_bf16.h>
#include <cstdint>
#include <cstddef>

#define NN   10000
#define NP   10048          // padding for the elementwise kernels (157*64)
#define NPG  10112          // padding for the GEMM/topk (79*128)
#define DD   128
#define NCAND 32

// ---------------- device scratch ----------------
__device__ float g_xn[(size_t)NPG*DD];              // normalized fp32
__device__ __nv_bfloat16 g_xh[(size_t)NPG*DD];      // bf16 of normalized
__device__ __nv_bfloat16 g_simh[(size_t)NPG*NPG];   // bf16 sim (202 MB)
__device__ int   g_cand[(size_t)NN*NCAND];
__device__ int   g_knn[(size_t)NN*16];
__device__ float g_mult[(size_t)2048*NP];           // [i][j][NP] per branch
__device__ float g_coef[(size_t)96*NP];             // [j][NP] per branch
__device__ float g_hyper[(size_t)NN*5*DD];

__device__ __forceinline__ uint32_t kmax32(uint32_t a, uint32_t b){ return a>b?a:b; }

// ---------------- normalize rows -> fp32 + bf16 ----------------
__global__ __launch_bounds__(256) void k_norm(const float* __restrict__ feats){
    int w = threadIdx.x >> 5, lane = threadIdx.x & 31;
    int row = blockIdx.x*8 + w;
    if (row >= NPG) return;
    float4 v = make_float4(0.f,0.f,0.f,0.f);
    if (row < NN){
        v = *(const float4*)(feats + (size_t)row*DD + lane*4);
        float ss = v.x*v.x + v.y*v.y + v.z*v.z + v.w*v.w;
        #pragma unroll
        for (int o=16;o;o>>=1) ss += __shfl_xor_sync(0xffffffffu, ss, o);
        float inv = 1.0f / fmaxf(sqrtf(ss), 1e-12f);
        v.x*=inv; v.y*=inv; v.z*=inv; v.w*=inv;
    }
    *(float4*)(g_xn + (size_t)row*DD + lane*4) = v;
    __nv_bfloat16 hi[4] = { __float2bfloat16_rn(v.x), __float2bfloat16_rn(v.y),
                            __float2bfloat16_rn(v.z), __float2bfloat16_rn(v.w) };
    *(uint2*)(g_xh + (size_t)row*DD + lane*4) = *(uint2*)hi;
}

// ---------------- approx sim = xh @ xh^T (single-pass bf16 HMMA) ----------
#define LDSM4(r0,r1,r2,r3,addr) \
    asm volatile("ldmatrix.sync.aligned.m8n8.x4.shared.b16 {%0,%1,%2,%3},[%4];" \
        : "=r"(r0),"=r"(r1),"=r"(r2),"=r"(r3) : "r"(addr))
#define LDSM2(r0,r1,addr) \
    asm volatile("ldmatrix.sync.aligned.m8n8.x2.shared.b16 {%0,%1},[%2];" \
        : "=r"(r0),"=r"(r1) : "r"(addr))
#define MMA16816(c,a,b) \
    asm volatile("mma.sync.aligned.m16n8k16.row.col.f32.bf16.bf16.f32 " \
        "{%0,%1,%2,%3},{%4,%5,%6,%7},{%8,%9},{%0,%1,%2,%3};" \
        : "+f"(c[0]),"+f"(c[1]),"+f"(c[2]),"+f"(c[3]) \
        : "r"(a[0]),"r"(a[1]),"r"(a[2]),"r"(a[3]),"r"(b[0]),"r"(b[1]))

#define SROW2 136        // smem row stride in bf16 (272B) — conflict-free ldmatrix
#define SIM_SMEM (2*128*SROW2*2)   // 69632 bytes

__global__ __launch_bounds__(256) void k_simT(){
    extern __shared__ __align__(16) char smem[];
    char* sA = smem;
    char* sB = smem + 128*SROW2*2;

    const int tid  = threadIdx.x;
    const int wid  = tid >> 5;
    const int lane = tid & 31;
    const int bm = blockIdx.y, bn = blockIdx.x;
    const int warpM = (wid & 3) * 32;
    const int warpN = (wid >> 2) * 64;

    float c[2][8][4];
    #pragma unroll
    for (int t=0;t<2;t++)
        #pragma unroll
        for (int j=0;j<8;j++)
            #pragma unroll
            for (int q=0;q<4;q++) c[t][j][q] = 0.f;

    #pragma unroll
    for (int i=0;i<8;i++){
        int e = tid + i*256;
        int r = e >> 4, c8 = e & 15;
        size_t ga = (size_t)(bm*128 + r)*DD + c8*8;
        size_t gb = (size_t)(bn*128 + r)*DD + c8*8;
        *(uint4*)(sA + (r*SROW2 + c8*8)*2) = *(const uint4*)(g_xh + ga);
        *(uint4*)(sB + (r*SROW2 + c8*8)*2) = *(const uint4*)(g_xh + gb);
    }
    __syncthreads();

    uint32_t aoff = (uint32_t)((warpM + (lane & 15))*SROW2*2 + (lane >> 4)*16);
    uint32_t boff = (uint32_t)((warpN + (lane & 7))*SROW2*2 + ((lane >> 3) & 1)*16);
    uint32_t sA_u = (uint32_t)__cvta_generic_to_shared(sA);
    uint32_t sB_u = (uint32_t)__cvta_generic_to_shared(sB);

    #pragma unroll
    for (int ks=0; ks<8; ks++){
        uint32_t ah[2][4];
        #pragma unroll
        for (int t=0;t<2;t++){
            uint32_t ad = aoff + t*(16*SROW2*2) + ks*32;
            LDSM4(ah[t][0],ah[t][1],ah[t][2],ah[t][3], sA_u + ad);
        }
        #pragma unroll
        for (int j=0;j<8;j++){
            uint32_t bh[2];
            uint32_t bd = boff + j*(8*SROW2*2) + ks*32;
            LDSM2(bh[0],bh[1], sB_u + bd);
            #pragma unroll
            for (int t=0;t<2;t++)
                MMA16816(c[t][j], ah[t], bh);
        }
    }

    const int r0 = bm*128 + warpM + (lane >> 2);
    const int c0 = bn*128 + warpN + (lane & 3)*2;
    #pragma unroll
    for (int t=0;t<2;t++){
        #pragma unroll
        for (int j=0;j<8;j++){
            size_t base = (size_t)(r0 + t*16)*NPG + c0 + j*8;
            *(__nv_bfloat162*)(g_simh + base) =
                __float22bfloat162_rn(make_float2(c[t][j][0], c[t][j][1]));
            *(__nv_bfloat162*)(g_simh + base + 8ull*NPG) =
                __float22bfloat162_rn(make_float2(c[t][j][2], c[t][j][3]));
        }
    }
}

// ---------------- per-row top-32 candidates (bf16 keys, u32 selection) -----
__device__ __forceinline__ uint32_t bf16key(uint32_t u16, int j){
    uint32_t m = (u16 & 0x8000u) ? ((~u16) & 0xFFFFu) : (u16 | 0x8000u);
    return (m << 14) | (uint32_t)(16383 - j);
}

__global__ __launch_bounds__(128) void k_topk(){
    __shared__ uint32_t sk[16][128];
    __shared__ uint32_t wmax[4];
    int row = blockIdx.x;
    int tid = threadIdx.x;
    const uint4* srow4 = (const uint4*)(g_simh + (size_t)row*NPG);

    uint32_t t[16];
    #pragma unroll
    for (int r=0;r<16;r++) t[r]=0u;

    #pragma unroll 1
    for (int it=0; it<10; it++){
        int v4 = it*128 + tid;
        if (v4 >= 1250) break;          // 1250*8 == 10000 exactly
        uint4 q = srow4[v4];
        int jb = v4*8;
        uint32_t ws[4] = {q.x, q.y, q.z, q.w};
        #pragma unroll
        for (int wv=0; wv<4; wv++){
            uint32_t klo = bf16key(ws[wv] & 0xFFFFu, jb + wv*2);
            uint32_t khi = bf16key(ws[wv] >> 16,     jb + wv*2 + 1);
            if (klo > t[15]){
                t[15] = klo;
                #pragma unroll
                for (int r=15;r>0;r--)
                    if (t[r] > t[r-1]){ uint32_t tmp=t[r-1]; t[r-1]=t[r]; t[r]=tmp; }
            }
            if (khi > t[15]){
                t[15] = khi;
                #pragma unroll
                for (int r=15;r>0;r--)
                    if (t[r] > t[r-1]){ uint32_t tmp=t[r-1]; t[r-1]=t[r]; t[r]=tmp; }
            }
        }
    }
    #pragma unroll
    for (int r=0;r<16;r++) sk[r][tid] = t[r];
    uint32_t lmax = t[0];               // t sorted desc
    __syncthreads();

    for (int sel=0; sel<NCAND; sel++){
        uint32_t m = lmax;
        #pragma unroll
        for (int o=16;o;o>>=1) m = kmax32(m, __shfl_xor_sync(0xffffffffu, m, o));
        if ((tid & 31) == 0) wmax[tid >> 5] = m;
        __syncthreads();
        uint32_t best = kmax32(kmax32(wmax[0],wmax[1]), kmax32(wmax[2],wmax[3]));
        if (lmax == best){
            #pragma unroll
            for (int r=0;r<16;r++){
                if (sk[r][tid] == best){ sk[r][tid] = 0u; break; }
            }
            uint32_t nm = 0u;
            #pragma unroll
            for (int r=0;r<16;r++) nm = kmax32(nm, sk[r][tid]);
            lmax = nm;
        }
        if (tid == 0) g_cand[(size_t)row*NCAND + sel] = 16383 - (int)(best & 16383u);
        __syncthreads();
    }
}

// ---------------- fp32 re-rank of 32 candidates -> top-16 ----------------
__global__ __launch_bounds__(256) void k_refine(){
    int w = threadIdx.x >> 5, lane = threadIdx.x & 31;
    int row = blockIdx.x*8 + w;
    if (row >= NN) return;
    float4 xr = *(const float4*)(g_xn + (size_t)row*DD + lane*4);
    int myidx = g_cand[(size_t)row*NCAND + lane];
    if ((unsigned)myidx >= (unsigned)NN) myidx = 0;
    unsigned long long mykey = 0ull;
    #pragma unroll 4
    for (int c=0; c<NCAND; c++){
        int cand = __shfl_sync(0xffffffffu, myidx, c);
        float4 xc = *(const float4*)(g_xn + (size_t)cand*DD + lane*4);
        float p = xr.x*xc.x + xr.y*xc.y + xr.z*xc.z + xr.w*xc.w;
        #pragma unroll
        for (int o=16;o;o>>=1) p += __shfl_xor_sync(0xffffffffu, p, o);
        if (lane == c){
            unsigned u = __float_as_uint(p);
            u = (u & 0x80000000u) ? ~u : (u | 0x80000000u);
            mykey = ((unsigned long long)u << 32) | (unsigned)(~(unsigned)myidx);
        }
    }
    int rank = 0;
    #pragma unroll
    for (int peer=0; peer<32; peer++){
        unsigned long long pk = __shfl_sync(0xffffffffu, mykey, peer);
        rank += (pk > mykey) ? 1 : 0;
    }
    if (rank < 16) g_knn[(size_t)row*16 + rank] = myidx;
}

// ---------------- mult logits: 4n x 4j register-tiled GEMM ----------------
// grid (40, K); block 256. n-tile 256, d-chunked (4 x 32d through smem).
#define XS_STRIDE 260
#define WT_STRIDE 20
template<int K>
__global__ __launch_bounds__(256) void k_mult(const float* __restrict__ feats,
                                              const int* __restrict__ idx,
                                              int stride, int off0,
                                              const float* __restrict__ wKK,
                                              const float* __restrict__ bKK,
                                              size_t moff){
    constexpr int NJC = K/16;
    __shared__ float xs[32*XS_STRIDE];          // [d in chunk][n], 33.3 KB
    __shared__ float wsT[NJC*32*WT_STRIDE];     // [jc][d][j]
    __shared__ int   sidx[256];

    const int tid = threadIdx.x;
    const int i  = blockIdx.y;
    const int n0 = blockIdx.x*256;
    const int tx = tid & 63;        // n-group: n = n0 + tx*4 + nn
    const int ty = tid >> 6;        // j-group: j = jc*16 + ty*4 + jj

    {
        int ng = n0 + tid;
        int s;
        if (idx == nullptr) s = (ng < NN) ? g_knn[(size_t)ng*16 + i] : 0;
        else                s = (ng < NN) ? idx[(size_t)ng*stride + off0 + i] : 0;
        if ((unsigned)s >= (unsigned)NN) s = 0;     // defensive clamp
        sidx[tid] = s;
    }

    float acc[NJC][4][4];
    #pragma unroll
    for (int jc=0;jc<NJC;jc++)
        #pragma unroll
        for (int a=0;a<4;a++)
            #pragma unroll
            for (int b=0;b<4;b++) acc[jc][a][b] = 0.f;

    #pragma unroll 1
    for (int chunk=0; chunk<4; chunk++){
        __syncthreads();
        // gather x chunk: 256 rows x 32 d, transposed into xs[d][n]
        #pragma unroll
        for (int p=0;p<8;p++){
            int e = tid + p*256;
            int row = e >> 3, d4 = e & 7;
            float4 v = *(const float4*)(feats + (size_t)sidx[row]*DD + chunk*32 + d4*4);
            xs[(d4*4+0)*XS_STRIDE + row] = v.x;
            xs[(d4*4+1)*XS_STRIDE + row] = v.y;
            xs[(d4*4+2)*XS_STRIDE + row] = v.z;
            xs[(d4*4+3)*XS_STRIDE + row] = v.w;
        }
        // weights chunk: wsT[jc][d][j]; per chunk each j-row contributes 8 float4
        for (int e=tid; e<NJC*128; e+=256){
            int jc = e >> 7;
            int j  = (e >> 3) & 15;
            int d4 = e & 7;
            float4 v = *(const float4*)(wKK + ((size_t)(i*K + jc*16 + j))*DD + chunk*32 + d4*4);
            wsT[jc*(32*WT_STRIDE) + (d4*4+0)*WT_STRIDE + j] = v.x;
            wsT[jc*(32*WT_STRIDE) + (d4*4+1)*WT_STRIDE + j] = v.y;
            wsT[jc*(32*WT_STRIDE) + (d4*4+2)*WT_STRIDE + j] = v.z;
            wsT[jc*(32*WT_STRIDE) + (d4*4+3)*WT_STRIDE + j] = v.w;
        }
        __syncthreads();

        #pragma unroll
        for (int d=0; d<32; d++){
            float4 xv = *(float4*)&xs[d*XS_STRIDE + tx*4];
            #pragma unroll
            for (int jc=0; jc<NJC; jc++){
                float4 wv = *(float4*)&wsT[jc*(32*WT_STRIDE) + d*WT_STRIDE + ty*4];
                acc[jc][0][0] += xv.x*wv.x; acc[jc][0][1] += xv.x*wv.y;
                acc[jc][0][2] += xv.x*wv.z; acc[jc][0][3] += xv.x*wv.w;
                acc[jc][1][0] += xv.y*wv.x; acc[jc][1][1] += xv.y*wv.y;
                acc[jc][1][2] += xv.y*wv.z; acc[jc][1][3] += xv.y*wv.w;
                acc[jc][2][0] += xv.z*wv.x; acc[jc][2][1] += xv.z*wv.y;
                acc[jc][2][2] += xv.z*wv.z; acc[jc][2][3] += xv.z*wv.w;
                acc[jc][3][0] += xv.w*wv.x; acc[jc][3][1] += xv.w*wv.y;
                acc[jc][3][2] += xv.w*wv.z; acc[jc][3][3] += xv.w*wv.w;
            }
        }
    }

    if (n0 + tx*4 < NP){
        #pragma unroll
        for (int jc=0; jc<NJC; jc++){
            #pragma unroll
            for (int jj=0; jj<4; jj++){
                int jglob = jc*16 + ty*4 + jj;
                float b = __ldg(&bKK[i*K + jglob]);
                *(float4*)(g_mult + moff + (size_t)(i*K + jglob)*NP + n0 + tx*4) =
                    make_float4(acc[jc][0][jj]+b, acc[jc][1][jj]+b,
                                acc[jc][2][jj]+b, acc[jc][3][jj]+b);
            }
        }
    }
}

// ---------------- coef[j][n] = sum_i wK1[i]*softmax_j(mult[i][:,n]) ---------
template<int K>
__device__ __forceinline__ void coef_body(int n, size_t moff, size_t coff,
                                          const float* __restrict__ wK1){
    const float* mout = g_mult + moff;
    float cacc[K];
    #pragma unroll
    for (int j=0;j<K;j++) cacc[j]=0.f;
    #pragma unroll
    for (int i=0;i<K;i++){
        float v[K];
        float m = -1e30f;
        #pragma unroll
        for (int j=0;j<K;j++){
            v[j] = mout[((size_t)(i*K + j))*NP + n];
            m = fmaxf(m, v[j]);
        }
        float s = 0.f;
        #pragma unroll
        for (int j=0;j<K;j++){ v[j] = __expf(v[j]-m); s += v[j]; }
        float w = wK1[i] / s;
        #pragma unroll
        for (int j=0;j<K;j++) cacc[j] += w * v[j];
    }
    float* cout = g_coef + coff;
    #pragma unroll
    for (int j=0;j<K;j++) cout[(size_t)j*NP + n] = cacc[j];
}

__global__ __launch_bounds__(256) void k_coef_all(const float* __restrict__ wK1_c,
                                                  const float* __restrict__ wK1_n,
                                                  const float* __restrict__ wK1_s){
    int n = blockIdx.x*256 + threadIdx.x;
    if (n >= NN) return;
    const size_t M16 = (size_t)256*NP;
    int br = blockIdx.y;
    if (br < 3)       coef_body<16>(n, (size_t)br*M16, (size_t)br*16*NP, wK1_c);
    else if (br == 3) coef_body<16>(n, 3*M16, (size_t)48*NP, wK1_n);
    else              coef_body<32>(n, 4*M16, (size_t)64*NP, wK1_s);
}

// ---------------- hyper[n][t][:] = sum_j coef[j][n]*feats[idx(n,j)] + bK1 ---
__global__ __launch_bounds__(256) void k_hyper_all(const float* __restrict__ feats,
                                                   const int* __restrict__ cidx,
                                                   const int* __restrict__ sidx,
                                                   const float* __restrict__ bK1_c,
                                                   const float* __restrict__ bK1_n,
                                                   const float* __restrict__ bK1_s){
    int w = threadIdx.x >> 5, lane = threadIdx.x & 31;
    int n = blockIdx.x*8 + w;
    if (n >= NN) return;
    int t = blockIdx.y;
    const int* idx; int stride, off0, K; const float* bK1; size_t coff;
    if (t < 3){ idx = cidx; stride = 48; off0 = t*16; K = 16; bK1 = bK1_c; coff = (size_t)t*16*NP; }
    else if (t == 3){ idx = g_knn; stride = 16; off0 = 0; K = 16; bK1 = bK1_n; coff = (size_t)48*NP; }
    else { idx = sidx; stride = 32; off0 = 0; K = 32; bK1 = bK1_s; coff = (size_t)64*NP; }

    const float* coef = g_coef + coff;
    float4 acc = make_float4(0.f,0.f,0.f,0.f);
    #pragma unroll 4
    for (int j=0;j<K;j++){
        float c = __ldg(&coef[(size_t)j*NP + n]);
        int src = idx[(size_t)n*stride + off0 + j];
        if ((unsigned)src >= (unsigned)NN) src = 0;
        float4 f = *(const float4*)(feats + (size_t)src*DD + lane*4);
        acc.x += c*f.x; acc.y += c*f.y; acc.z += c*f.z; acc.w += c*f.w;
    }
    float b = bK1[0];
    acc.x += b; acc.y += b; acc.z += b; acc.w += b;
    *(float4*)(g_hyper + ((size_t)n*5 + t)*DD + lane*4) = acc;
}

// ---------------- EdgeConv attention + final FC ----------------
__global__ __launch_bounds__(128) void k_final(const float* __restrict__ ec_w1,
                                               const float* __restrict__ ec_b1,
                                               const float* __restrict__ ec_w2,
                                               const float* __restrict__ ec_b2,
                                               const float* __restrict__ fc_w,
                                               const float* __restrict__ fc_b,
                                               float* __restrict__ out){
    extern __shared__ float fsm[];
    float* fcw  = fsm;
    float* w1s  = fsm + 16384;
    float* xs   = fsm + 16384 + 4096;
    float* aggs = xs + 4*640;
    int tid = threadIdx.x;
    for (int e=tid; e<16384/4; e+=128)
        *(float4*)&fcw[e*4] = *(const float4*)&fc_w[e*4];
    for (int e=tid; e<4096/4; e+=128)
        *(float4*)&w1s[e*4] = *(const float4*)&ec_w1[e*4];
    __syncthreads();

    int w = tid >> 5, lane = tid & 31;
    int n = blockIdx.x*4 + w;

    float4 xr[5];
    #pragma unroll
    for (int t=0;t<5;t++){
        xr[t] = *(const float4*)(g_hyper + ((size_t)n*5 + t)*DD + lane*4);
        *(float4*)&xs[w*640 + t*128 + lane*4] = xr[t];
    }
    __syncwarp();

    float w2v = ec_w2[lane];
    float b1v = ec_b1[lane];
    float sc[5];
    #pragma unroll
    for (int t=0;t<5;t++){
        float h = b1v;
        #pragma unroll 4
        for (int d=0; d<DD; d++)
            h += xs[w*640 + t*128 + d] * w1s[d*32 + lane];
        h = fmaxf(h, 0.f);
        float p = h * w2v;
        #pragma unroll
        for (int o=16;o;o>>=1) p += __shfl_xor_sync(0xffffffffu, p, o);
        sc[t] = p;
    }
    float b2 = ec_b2[0];
    float m = -1e30f;
    #pragma unroll
    for (int t=0;t<5;t++){ sc[t] += b2; m = fmaxf(m, sc[t]); }
    float s = 0.f;
    #pragma unroll
    for (int t=0;t<5;t++){ sc[t] = __expf(sc[t]-m); s += sc[t]; }
    float inv = 1.f/s;
    #pragma unroll
    for (int t=0;t<5;t++) sc[t] *= inv;

    float4 a = make_float4(0.f,0.f,0.f,0.f);
    #pragma unroll
    for (int t=0;t<5;t++){
        a.x += sc[t]*xr[t].x; a.y += sc[t]*xr[t].y;
        a.z += sc[t]*xr[t].z; a.w += sc[t]*xr[t].w;
    }
    *(float4*)&aggs[w*128 + lane*4] = a;
    __syncwarp();

    float4 o = *(const float4*)&fc_b[lane*4];
    #pragma unroll 4
    for (int d=0; d<DD; d++){
        float av = aggs[w*128 + d];
        float4 fw = *(const float4*)&fcw[d*128 + lane*4];
        o.x += av*fw.x; o.y += av*fw.y; o.z += av*fw.z; o.w += av*fw.w;
    }
    o.x = fmaxf(o.x,0.f); o.y = fmaxf(o.y,0.f);
    o.z = fmaxf(o.z,0.f); o.w = fmaxf(o.w,0.f);
    *(float4*)(out + (size_t)n*DD + lane*4) = o;
}

// ---------------- launch ----------------
extern "C" void kernel_launch(void* const* d_in, const int* in_sizes, int n_in,
                              void* d_out, int out_size){
    const float* feats  = (const float*)d_in[1];
    const int*   cidx   = (const int*)d_in[2];
    const int*   sidx   = (const int*)d_in[3];
    const float* wKK_c  = (const float*)d_in[5];
    const float* bKK_c  = (const float*)d_in[6];
    const float* wK1_c  = (const float*)d_in[7];
    const float* bK1_c  = (const float*)d_in[8];
    const float* wKK_n  = (const float*)d_in[9];
    const float* bKK_n  = (const float*)d_in[10];
    const float* wK1_n  = (const float*)d_in[11];
    const float* bK1_n  = (const float*)d_in[12];
    const float* wKK_s  = (const float*)d_in[13];
    const float* bKK_s  = (const float*)d_in[14];
    const float* wK1_s  = (const float*)d_in[15];
    const float* bK1_s  = (const float*)d_in[16];
    const float* ec_w1  = (const float*)d_in[17];
    const float* ec_b1  = (const float*)d_in[18];
    const float* ec_w2  = (const float*)d_in[19];
    const float* ec_b2  = (const float*)d_in[20];
    const float* fc_w   = (const float*)d_in[21];
    const float* fc_b   = (const float*)d_in[22];
    float* out = (float*)d_out;

    cudaFuncSetAttribute(k_simT, cudaFuncAttributeMaxDynamicSharedMemorySize, SIM_SMEM);
    cudaFuncSetAttribute(k_final, cudaFuncAttributeMaxDynamicSharedMemorySize, 94208);

    k_norm<<<NPG/8, 256>>>(feats);
    k_simT<<<dim3(NPG/128, NPG/128), 256, SIM_SMEM>>>();
    k_topk<<<NN, 128>>>();
    k_refine<<<(NN+7)/8, 256>>>();

    const size_t M16 = (size_t)256*NP;
    for (int c=0;c<3;c++)
        k_mult<16><<<dim3(40,16),256>>>(feats, cidx, 48, c*16, wKK_c, bKK_c, (size_t)c*M16);
    k_mult<16><<<dim3(40,16),256>>>(feats, nullptr, 16, 0, wKK_n, bKK_n, 3*M16);
    k_mult<32><<<dim3(40,32),256>>>(feats, sidx, 32, 0, wKK_s, bKK_s, 4*M16);

    int cb = (NN + 255)/256;
    k_coef_all<<<dim3(cb,5),256>>>(wK1_c, wK1_n, wK1_s);

    k_hyper_all<<<dim3(NN/8,5),256>>>(feats, cidx, sidx, bK1_c, bK1_n, bK1_s);

    k_final<<<NN/4, 128, 94208>>>(ec_w1, ec_b1, ec_w2, ec_b2, fc_w, fc_b, out);
}

// round 15
// speedup vs baseline: 1.1941x; 1.0542x over previous
#include <cuda_runtime.h>
#include <cuda_bf16.h>
#include <cstdint>
#include <cstddef>

#define NN   10000
#define NP   10048          // padding for the elementwise kernels (157*64)
#define NPG  10112          // padding for the GEMM/topk (79*128)
#define DD   128
#define NCAND 32

// ---------------- device scratch ----------------
__device__ float g_xn[(size_t)NPG*DD];              // normalized fp32
__device__ __nv_bfloat16 g_xh[(size_t)NPG*DD];      // bf16 of normalized
__device__ __nv_bfloat16 g_simh[(size_t)NPG*NPG];   // bf16 sim (202 MB)
__device__ int   g_cand[(size_t)NN*NCAND];
__device__ int   g_knn[(size_t)NN*16];
__device__ float g_mult[(size_t)2048*NP];           // [i][j][NP] per branch
__device__ float g_coef[(size_t)96*NP];             // [j][NP] per branch
__device__ float g_hyper[(size_t)NN*5*DD];

__device__ __forceinline__ uint32_t kmax32(uint32_t a, uint32_t b){ return a>b?a:b; }

// ---------------- normalize rows -> fp32 + bf16 ----------------
__global__ __launch_bounds__(256) void k_norm(const float* __restrict__ feats){
    int w = threadIdx.x >> 5, lane = threadIdx.x & 31;
    int row = blockIdx.x*8 + w;
    if (row >= NPG) return;
    float4 v = make_float4(0.f,0.f,0.f,0.f);
    if (row < NN){
        v = *(const float4*)(feats + (size_t)row*DD + lane*4);
        float ss = v.x*v.x + v.y*v.y + v.z*v.z + v.w*v.w;
        #pragma unroll
        for (int o=16;o;o>>=1) ss += __shfl_xor_sync(0xffffffffu, ss, o);
        float inv = 1.0f / fmaxf(sqrtf(ss), 1e-12f);
        v.x*=inv; v.y*=inv; v.z*=inv; v.w*=inv;
    }
    *(float4*)(g_xn + (size_t)row*DD + lane*4) = v;
    __nv_bfloat16 hi[4] = { __float2bfloat16_rn(v.x), __float2bfloat16_rn(v.y),
                            __float2bfloat16_rn(v.z), __float2bfloat16_rn(v.w) };
    *(uint2*)(g_xh + (size_t)row*DD + lane*4) = *(uint2*)hi;
}

// ---------------- approx sim = xh @ xh^T (symmetric, bf16 HMMA) ----------
#define LDSM4(r0,r1,r2,r3,addr) \
    asm volatile("ldmatrix.sync.aligned.m8n8.x4.shared.b16 {%0,%1,%2,%3},[%4];" \
        : "=r"(r0),"=r"(r1),"=r"(r2),"=r"(r3) : "r"(addr))
#define LDSM2(r0,r1,addr) \
    asm volatile("ldmatrix.sync.aligned.m8n8.x2.shared.b16 {%0,%1},[%2];" \
        : "=r"(r0),"=r"(r1) : "r"(addr))
#define MMA16816(c,a,b) \
    asm volatile("mma.sync.aligned.m16n8k16.row.col.f32.bf16.bf16.f32 " \
        "{%0,%1,%2,%3},{%4,%5,%6,%7},{%8,%9},{%0,%1,%2,%3};" \
        : "+f"(c[0]),"+f"(c[1]),"+f"(c[2]),"+f"(c[3]) \
        : "r"(a[0]),"r"(a[1]),"r"(a[2]),"r"(a[3]),"r"(b[0]),"r"(b[1]))

#define SROW2 136        // smem row stride in bf16 (272B) — conflict-free ldmatrix
#define SIM_SMEM (2*128*SROW2*2)   // 69632 bytes

__global__ __launch_bounds__(256) void k_simT(){
    extern __shared__ __align__(16) char smem[];
    char* sA = smem;
    char* sB = smem + 128*SROW2*2;

    const int bm = blockIdx.y, bn = blockIdx.x;
    if (bm > bn) return;                 // symmetric: upper triangle only

    const int tid  = threadIdx.x;
    const int wid  = tid >> 5;
    const int lane = tid & 31;
    const int warpM = (wid & 3) * 32;
    const int warpN = (wid >> 2) * 64;

    float c[2][8][4];
    #pragma unroll
    for (int t=0;t<2;t++)
        #pragma unroll
        for (int j=0;j<8;j++)
            #pragma unroll
            for (int q=0;q<4;q++) c[t][j][q] = 0.f;

    #pragma unroll
    for (int i=0;i<8;i++){
        int e = tid + i*256;
        int r = e >> 4, c8 = e & 15;
        size_t ga = (size_t)(bm*128 + r)*DD + c8*8;
        size_t gb = (size_t)(bn*128 + r)*DD + c8*8;
        *(uint4*)(sA + (r*SROW2 + c8*8)*2) = *(const uint4*)(g_xh + ga);
        *(uint4*)(sB + (r*SROW2 + c8*8)*2) = *(const uint4*)(g_xh + gb);
    }
    __syncthreads();

    uint32_t aoff = (uint32_t)((warpM + (lane & 15))*SROW2*2 + (lane >> 4)*16);
    uint32_t boff = (uint32_t)((warpN + (lane & 7))*SROW2*2 + ((lane >> 3) & 1)*16);
    uint32_t sA_u = (uint32_t)__cvta_generic_to_shared(sA);
    uint32_t sB_u = (uint32_t)__cvta_generic_to_shared(sB);

    #pragma unroll
    for (int ks=0; ks<8; ks++){
        uint32_t ah[2][4];
        #pragma unroll
        for (int t=0;t<2;t++){
            uint32_t ad = aoff + t*(16*SROW2*2) + ks*32;
            LDSM4(ah[t][0],ah[t][1],ah[t][2],ah[t][3], sA_u + ad);
        }
        #pragma unroll
        for (int j=0;j<8;j++){
            uint32_t bh[2];
            uint32_t bd = boff + j*(8*SROW2*2) + ks*32;
            LDSM2(bh[0],bh[1], sB_u + bd);
            #pragma unroll
            for (int t=0;t<2;t++)
                MMA16816(c[t][j], ah[t], bh);
        }
    }

    // direct write to (bm, bn)
    const int r0 = warpM + (lane >> 2);
    const int c0 = warpN + (lane & 3)*2;
    #pragma unroll
    for (int t=0;t<2;t++){
        #pragma unroll
        for (int j=0;j<8;j++){
            size_t base = (size_t)(bm*128 + r0 + t*16)*NPG + bn*128 + c0 + j*8;
            *(__nv_bfloat162*)(g_simh + base) =
                __float22bfloat162_rn(make_float2(c[t][j][0], c[t][j][1]));
            *(__nv_bfloat162*)(g_simh + base + 8ull*NPG) =
                __float22bfloat162_rn(make_float2(c[t][j][2], c[t][j][3]));
        }
    }

    // transposed write to (bn, bm) via smem staging (aliases sA/sB, dead now)
    if (bm != bn){
        __syncthreads();                       // all warps done reading sA/sB
        __nv_bfloat16* st = (__nv_bfloat16*)smem;   // [128 cols][SROW2] -> st[cl][rl]
        #pragma unroll
        for (int t=0;t<2;t++){
            #pragma unroll
            for (int j=0;j<8;j++){
                #pragma unroll
                for (int q=0;q<4;q++){
                    int rl = r0 + t*16 + (q>>1)*8;
                    int cl = c0 + j*8 + (q&1);
                    st[cl*SROW2 + rl] = __float2bfloat16_rn(c[t][j][q]);
                }
            }
        }
        __syncthreads();
        for (int e=tid; e<128*16; e+=256){
            int r = e >> 4, s8 = e & 15;
            uint4 v = *(uint4*)&st[r*SROW2 + s8*8];
            *(uint4*)(g_simh + (size_t)(bn*128 + r)*NPG + bm*128 + s8*8) = v;
        }
    }
}

// ---------------- per-row top-32 candidates (bf16 keys, u32 selection) -----
__device__ __forceinline__ uint32_t bf16key(uint32_t u16, int j){
    uint32_t m = (u16 & 0x8000u) ? ((~u16) & 0xFFFFu) : (u16 | 0x8000u);
    return (m << 14) | (uint32_t)(16383 - j);
}

__global__ __launch_bounds__(128) void k_topk(){
    __shared__ uint32_t sk[16][128];
    __shared__ uint32_t wmax[4];
    int row = blockIdx.x;
    int tid = threadIdx.x;
    const uint4* srow4 = (const uint4*)(g_simh + (size_t)row*NPG);

    uint32_t t[16];
    #pragma unroll
    for (int r=0;r<16;r++) t[r]=0u;

    #pragma unroll 1
    for (int it=0; it<10; it++){
        int v4 = it*128 + tid;
        if (v4 >= 1250) break;          // 1250*8 == 10000 exactly
        uint4 q = srow4[v4];
        int jb = v4*8;
        uint32_t ws[4] = {q.x, q.y, q.z, q.w};
        #pragma unroll
        for (int wv=0; wv<4; wv++){
            uint32_t klo = bf16key(ws[wv] & 0xFFFFu, jb + wv*2);
            uint32_t khi = bf16key(ws[wv] >> 16,     jb + wv*2 + 1);
            if (klo > t[15]){
                t[15] = klo;
                #pragma unroll
                for (int r=15;r>0;r--)
                    if (t[r] > t[r-1]){ uint32_t tmp=t[r-1]; t[r-1]=t[r]; t[r]=tmp; }
            }
            if (khi > t[15]){
                t[15] = khi;
                #pragma unroll
                for (int r=15;r>0;r--)
                    if (t[r] > t[r-1]){ uint32_t tmp=t[r-1]; t[r-1]=t[r]; t[r]=tmp; }
            }
        }
    }
    #pragma unroll
    for (int r=0;r<16;r++) sk[r][tid] = t[r];
    uint32_t lmax = t[0];               // t sorted desc
    __syncthreads();

    for (int sel=0; sel<NCAND; sel++){
        uint32_t m = lmax;
        #pragma unroll
        for (int o=16;o;o>>=1) m = kmax32(m, __shfl_xor_sync(0xffffffffu, m, o));
        if ((tid & 31) == 0) wmax[tid >> 5] = m;
        __syncthreads();
        uint32_t best = kmax32(kmax32(wmax[0],wmax[1]), kmax32(wmax[2],wmax[3]));
        if (lmax == best){
            #pragma unroll
            for (int r=0;r<16;r++){
                if (sk[r][tid] == best){ sk[r][tid] = 0u; break; }
            }
            uint32_t nm = 0u;
            #pragma unroll
            for (int r=0;r<16;r++) nm = kmax32(nm, sk[r][tid]);
            lmax = nm;
        }
        if (tid == 0) g_cand[(size_t)row*NCAND + sel] = 16383 - (int)(best & 16383u);
        __syncthreads();
    }
}

// ---------------- fp32 re-rank of 32 candidates -> top-16 ----------------
__global__ __launch_bounds__(256) void k_refine(){
    int w = threadIdx.x >> 5, lane = threadIdx.x & 31;
    int row = blockIdx.x*8 + w;
    if (row >= NN) return;
    float4 xr = *(const float4*)(g_xn + (size_t)row*DD + lane*4);
    int myidx = g_cand[(size_t)row*NCAND + lane];
    if ((unsigned)myidx >= (unsigned)NN) myidx = 0;
    unsigned long long mykey = 0ull;
    #pragma unroll 4
    for (int c=0; c<NCAND; c++){
        int cand = __shfl_sync(0xffffffffu, myidx, c);
        float4 xc = *(const float4*)(g_xn + (size_t)cand*DD + lane*4);
        float p = xr.x*xc.x + xr.y*xc.y + xr.z*xc.z + xr.w*xc.w;
        #pragma unroll
        for (int o=16;o;o>>=1) p += __shfl_xor_sync(0xffffffffu, p, o);
        if (lane == c){
            unsigned u = __float_as_uint(p);
            u = (u & 0x80000000u) ? ~u : (u | 0x80000000u);
            mykey = ((unsigned long long)u << 32) | (unsigned)(~(unsigned)myidx);
        }
    }
    int rank = 0;
    #pragma unroll
    for (int peer=0; peer<32; peer++){
        unsigned long long pk = __shfl_sync(0xffffffffu, mykey, peer);
        rank += (pk > mykey) ? 1 : 0;
    }
    if (rank < 16) g_knn[(size_t)row*16 + rank] = myidx;
}

// ---------------- mult logits: 4n x 4j register-tiled GEMM ----------------
// grid (40, K); block 256. n-tile 256, d-chunked (4 x 32d through smem).
#define XS_STRIDE 260
#define WT_STRIDE 20
template<int K>
__global__ __launch_bounds__(256) void k_mult(const float* __restrict__ feats,
                                              const int* __restrict__ idx,
                                              int stride, int off0,
                                              const float* __restrict__ wKK,
                                              const float* __restrict__ bKK,
                                              size_t moff){
    constexpr int NJC = K/16;
    __shared__ float xs[32*XS_STRIDE];          // [d in chunk][n], 33.3 KB
    __shared__ float wsT[NJC*32*WT_STRIDE];     // [jc][d][j]
    __shared__ int   sidx[256];

    const int tid = threadIdx.x;
    const int i  = blockIdx.y;
    const int n0 = blockIdx.x*256;
    const int tx = tid & 63;        // n-group: n = n0 + tx*4 + nn
    const int ty = tid >> 6;        // j-group: j = jc*16 + ty*4 + jj

    {
        int ng = n0 + tid;
        int s;
        if (idx == nullptr) s = (ng < NN) ? g_knn[(size_t)ng*16 + i] : 0;
        else                s = (ng < NN) ? idx[(size_t)ng*stride + off0 + i] : 0;
        if ((unsigned)s >= (unsigned)NN) s = 0;     // defensive clamp
        sidx[tid] = s;
    }

    float acc[NJC][4][4];
    #pragma unroll
    for (int jc=0;jc<NJC;jc++)
        #pragma unroll
        for (int a=0;a<4;a++)
            #pragma unroll
            for (int b=0;b<4;b++) acc[jc][a][b] = 0.f;

    #pragma unroll 1
    for (int chunk=0; chunk<4; chunk++){
        __syncthreads();
        // gather x chunk: 256 rows x 32 d, transposed into xs[d][n]
        #pragma unroll
        for (int p=0;p<8;p++){
            int e = tid + p*256;
            int row = e >> 3, d4 = e & 7;
            float4 v = *(const float4*)(feats + (size_t)sidx[row]*DD + chunk*32 + d4*4);
            xs[(d4*4+0)*XS_STRIDE + row] = v.x;
            xs[(d4*4+1)*XS_STRIDE + row] = v.y;
            xs[(d4*4+2)*XS_STRIDE + row] = v.z;
            xs[(d4*4+3)*XS_STRIDE + row] = v.w;
        }
        // weights chunk: wsT[jc][d][j]; per chunk each j-row contributes 8 float4
        for (int e=tid; e<NJC*128; e+=256){
            int jc = e >> 7;
            int j  = (e >> 3) & 15;
            int d4 = e & 7;
            float4 v = *(const float4*)(wKK + ((size_t)(i*K + jc*16 + j))*DD + chunk*32 + d4*4);
            wsT[jc*(32*WT_STRIDE) + (d4*4+0)*WT_STRIDE + j] = v.x;
            wsT[jc*(32*WT_STRIDE) + (d4*4+1)*WT_STRIDE + j] = v.y;
            wsT[jc*(32*WT_STRIDE) + (d4*4+2)*WT_STRIDE + j] = v.z;
            wsT[jc*(32*WT_STRIDE) + (d4*4+3)*WT_STRIDE + j] = v.w;
        }
        __syncthreads();

        #pragma unroll
        for (int d=0; d<32; d++){
            float4 xv = *(float4*)&xs[d*XS_STRIDE + tx*4];
            #pragma unroll
            for (int jc=0; jc<NJC; jc++){
                float4 wv = *(float4*)&wsT[jc*(32*WT_STRIDE) + d*WT_STRIDE + ty*4];
                acc[jc][0][0] += xv.x*wv.x; acc[jc][0][1] += xv.x*wv.y;
                acc[jc][0][2] += xv.x*wv.z; acc[jc][0][3] += xv.x*wv.w;
                acc[jc][1][0] += xv.y*wv.x; acc[jc][1][1] += xv.y*wv.y;
                acc[jc][1][2] += xv.y*wv.z; acc[jc][1][3] += xv.y*wv.w;
                acc[jc][2][0] += xv.z*wv.x; acc[jc][2][1] += xv.z*wv.y;
                acc[jc][2][2] += xv.z*wv.z; acc[jc][2][3] += xv.z*wv.w;
                acc[jc][3][0] += xv.w*wv.x; acc[jc][3][1] += xv.w*wv.y;
                acc[jc][3][2] += xv.w*wv.z; acc[jc][3][3] += xv.w*wv.w;
            }
        }
    }

    if (n0 + tx*4 < NP){
        #pragma unroll
        for (int jc=0; jc<NJC; jc++){
            #pragma unroll
            for (int jj=0; jj<4; jj++){
                int jglob = jc*16 + ty*4 + jj;
                float b = __ldg(&bKK[i*K + jglob]);
                *(float4*)(g_mult + moff + (size_t)(i*K + jglob)*NP + n0 + tx*4) =
                    make_float4(acc[jc][0][jj]+b, acc[jc][1][jj]+b,
                                acc[jc][2][jj]+b, acc[jc][3][jj]+b);
            }
        }
    }
}

// ---------------- coef[j][n] = sum_i wK1[i]*softmax_j(mult[i][:,n]) ---------
template<int K>
__device__ __forceinline__ void coef_body(int n, size_t moff, size_t coff,
                                          const float* __restrict__ wK1){
    const float* mout = g_mult + moff;
    float cacc[K];
    #pragma unroll
    for (int j=0;j<K;j++) cacc[j]=0.f;
    #pragma unroll
    for (int i=0;i<K;i++){
        float v[K];
        float m = -1e30f;
        #pragma unroll
        for (int j=0;j<K;j++){
            v[j] = mout[((size_t)(i*K + j))*NP + n];
            m = fmaxf(m, v[j]);
        }
        float s = 0.f;
        #pragma unroll
        for (int j=0;j<K;j++){ v[j] = __expf(v[j]-m); s += v[j]; }
        float w = wK1[i] / s;
        #pragma unroll
        for (int j=0;j<K;j++) cacc[j] += w * v[j];
    }
    float* cout = g_coef + coff;
    #pragma unroll
    for (int j=0;j<K;j++) cout[(size_t)j*NP + n] = cacc[j];
}

__global__ __launch_bounds__(256) void k_coef_all(const float* __restrict__ wK1_c,
                                                  const float* __restrict__ wK1_n,
                                                  const float* __restrict__ wK1_s){
    int n = blockIdx.x*256 + threadIdx.x;
    if (n >= NN) return;
    const size_t M16 = (size_t)256*NP;
    int br = blockIdx.y;
    if (br < 3)       coef_body<16>(n, (size_t)br*M16, (size_t)br*16*NP, wK1_c);
    else if (br == 3) coef_body<16>(n, 3*M16, (size_t)48*NP, wK1_n);
    else              coef_body<32>(n, 4*M16, (size_t)64*NP, wK1_s);
}

// ---------------- hyper[n][t][:] = sum_j coef[j][n]*feats[idx(n,j)] + bK1 ---
__global__ __launch_bounds__(256) void k_hyper_all(const float* __restrict__ feats,
                                                   const int* __restrict__ cidx,
                                                   const int* __restrict__ sidx,
                                                   const float* __restrict__ bK1_c,
                                                   const float* __restrict__ bK1_n,
                                                   const float* __restrict__ bK1_s){
    int w = threadIdx.x >> 5, lane = threadIdx.x & 31;
    int n = blockIdx.x*8 + w;
    if (n >= NN) return;
    int t = blockIdx.y;
    const int* idx; int stride, off0, K; const float* bK1; size_t coff;
    if (t < 3){ idx = cidx; stride = 48; off0 = t*16; K = 16; bK1 = bK1_c; coff = (size_t)t*16*NP; }
    else if (t == 3){ idx = g_knn; stride = 16; off0 = 0; K = 16; bK1 = bK1_n; coff = (size_t)48*NP; }
    else { idx = sidx; stride = 32; off0 = 0; K = 32; bK1 = bK1_s; coff = (size_t)64*NP; }

    const float* coef = g_coef + coff;
    float4 acc = make_float4(0.f,0.f,0.f,0.f);
    #pragma unroll 4
    for (int j=0;j<K;j++){
        float c = __ldg(&coef[(size_t)j*NP + n]);
        int src = idx[(size_t)n*stride + off0 + j];
        if ((unsigned)src >= (unsigned)NN) src = 0;
        float4 f = *(const float4*)(feats + (size_t)src*DD + lane*4);
        acc.x += c*f.x; acc.y += c*f.y; acc.z += c*f.z; acc.w += c*f.w;
    }
    float b = bK1[0];
    acc.x += b; acc.y += b; acc.z += b; acc.w += b;
    *(float4*)(g_hyper + ((size_t)n*5 + t)*DD + lane*4) = acc;
}

// ---------------- EdgeConv attention + final FC ----------------
__global__ __launch_bounds__(128) void k_final(const float* __restrict__ ec_w1,
                                               const float* __restrict__ ec_b1,
                                               const float* __restrict__ ec_w2,
                                               const float* __restrict__ ec_b2,
                                               const float* __restrict__ fc_w,
                                               const float* __restrict__ fc_b,
                                               float* __restrict__ out){
    extern __shared__ float fsm[];
    float* fcw  = fsm;
    float* w1s  = fsm + 16384;
    float* xs   = fsm + 16384 + 4096;
    float* aggs = xs + 4*640;
    int tid = threadIdx.x;
    for (int e=tid; e<16384/4; e+=128)
        *(float4*)&fcw[e*4] = *(const float4*)&fc_w[e*4];
    for (int e=tid; e<4096/4; e+=128)
        *(float4*)&w1s[e*4] = *(const float4*)&ec_w1[e*4];
    __syncthreads();

    int w = tid >> 5, lane = tid & 31;
    int n = blockIdx.x*4 + w;

    float4 xr[5];
    #pragma unroll
    for (int t=0;t<5;t++){
        xr[t] = *(const float4*)(g_hyper + ((size_t)n*5 + t)*DD + lane*4);
        *(float4*)&xs[w*640 + t*128 + lane*4] = xr[t];
    }
    __syncwarp();

    float w2v = ec_w2[lane];
    float b1v = ec_b1[lane];
    float sc[5];
    #pragma unroll
    for (int t=0;t<5;t++){
        float h = b1v;
        #pragma unroll 4
        for (int d=0; d<DD; d++)
            h += xs[w*640 + t*128 + d] * w1s[d*32 + lane];
        h = fmaxf(h, 0.f);
        float p = h * w2v;
        #pragma unroll
        for (int o=16;o;o>>=1) p += __shfl_xor_sync(0xffffffffu, p, o);
        sc[t] = p;
    }
    float b2 = ec_b2[0];
    float m = -1e30f;
    #pragma unroll
    for (int t=0;t<5;t++){ sc[t] += b2; m = fmaxf(m, sc[t]); }
    float s = 0.f;
    #pragma unroll
    for (int t=0;t<5;t++){ sc[t] = __expf(sc[t]-m); s += sc[t]; }
    float inv = 1.f/s;
    #pragma unroll
    for (int t=0;t<5;t++) sc[t] *= inv;

    float4 a = make_float4(0.f,0.f,0.f,0.f);
    #pragma unroll
    for (int t=0;t<5;t++){
        a.x += sc[t]*xr[t].x; a.y += sc[t]*xr[t].y;
        a.z += sc[t]*xr[t].z; a.w += sc[t]*xr[t].w;
    }
    *(float4*)&aggs[w*128 + lane*4] = a;
    __syncwarp();

    float4 o = *(const float4*)&fc_b[lane*4];
    #pragma unroll 4
    for (int d=0; d<DD; d++){
        float av = aggs[w*128 + d];
        float4 fw = *(const float4*)&fcw[d*128 + lane*4];
        o.x += av*fw.x; o.y += av*fw.y; o.z += av*fw.z; o.w += av*fw.w;
    }
    o.x = fmaxf(o.x,0.f); o.y = fmaxf(o.y,0.f);
    o.z = fmaxf(o.z,0.f); o.w = fmaxf(o.w,0.f);
    *(float4*)(out + (size_t)n*DD + lane*4) = o;
}

// ---------------- launch ----------------
extern "C" void kernel_launch(void* const* d_in, const int* in_sizes, int n_in,
                              void* d_out, int out_size){
    const float* feats  = (const float*)d_in[1];
    const int*   cidx   = (const int*)d_in[2];
    const int*   sidx   = (const int*)d_in[3];
    const float* wKK_c  = (const float*)d_in[5];
    const float* bKK_c  = (const float*)d_in[6];
    const float* wK1_c  = (const float*)d_in[7];
    const float* bK1_c  = (const float*)d_in[8];
    const float* wKK_n  = (const float*)d_in[9];
    const float* bKK_n  = (const float*)d_in[10];
    const float* wK1_n  = (const float*)d_in[11];
    const float* bK1_n  = (const float*)d_in[12];
    const float* wKK_s  = (const float*)d_in[13];
    const float* bKK_s  = (const float*)d_in[14];
    const float* wK1_s  = (const float*)d_in[15];
    const float* bK1_s  = (const float*)d_in[16];
    const float* ec_w1  = (const float*)d_in[17];
    const float* ec_b1  = (const float*)d_in[18];
    const float* ec_w2  = (const float*)d_in[19];
    const float* ec_b2  = (const float*)d_in[20];
    const float* fc_w   = (const float*)d_in[21];
    const float* fc_b   = (const float*)d_in[22];
    float* out = (float*)d_out;

    cudaFuncSetAttribute(k_simT, cudaFuncAttributeMaxDynamicSharedMemorySize, SIM_SMEM);
    cudaFuncSetAttribute(k_final, cudaFuncAttributeMaxDynamicSharedMemorySize, 94208);

    k_norm<<<NPG/8, 256>>>(feats);
    k_simT<<<dim3(NPG/128, NPG/128), 256, SIM_SMEM>>>();
    k_topk<<<NN, 128>>>();
    k_refine<<<(NN+7)/8, 256>>>();

    const size_t M16 = (size_t)256*NP;
    for (int c=0;c<3;c++)
        k_mult<16><<<dim3(40,16),256>>>(feats, cidx, 48, c*16, wKK_c, bKK_c, (size_t)c*M16);
    k_mult<16><<<dim3(40,16),256>>>(feats, nullptr, 16, 0, wKK_n, bKK_n, 3*M16);
    k_mult<32><<<dim3(40,32),256>>>(feats, sidx, 32, 0, wKK_s, bKK_s, 4*M16);

    int cb = (NN + 255)/256;
    k_coef_all<<<dim3(cb,5),256>>>(wK1_c, wK1_n, wK1_s);

    k_hyper_all<<<dim3(NN/8,5),256>>>(feats, cidx, sidx, bK1_c, bK1_n, bK1_s);

    k_final<<<NN/4, 128, 94208>>>(ec_w1, ec_b1, ec_w2, ec_b2, fc_w, fc_b, out);
}

// round 16
// speedup vs baseline: 1.3265x; 1.1109x over previous
#include <cuda_runtime.h>
#include <cuda_bf16.h>
#include <cstdint>
#include <cstddef>

#define NN   10000
#define NP   10048          // padding for the elementwise kernels (157*64)
#define NPG  10112          // padding for the GEMM/topk (79*128)
#define DD   128
#define NCAND 32

// ---------------- device scratch ----------------
__device__ float g_xn[(size_t)NPG*DD];              // normalized fp32
__device__ __nv_bfloat16 g_xh[(size_t)NPG*DD];      // bf16 of normalized
__device__ __nv_bfloat16 g_simh[(size_t)NPG*NPG];   // bf16 sim (202 MB)
__device__ int   g_cand[(size_t)NN*NCAND];
__device__ int   g_knn[(size_t)NN*16];
__device__ float g_mult[(size_t)2048*NP];           // [i][j][NP] per branch
__device__ float g_coef[(size_t)96*NP];             // [j][NP] per branch
__device__ float g_hyper[(size_t)NN*5*DD];

__device__ __forceinline__ uint32_t kmax32(uint32_t a, uint32_t b){ return a>b?a:b; }

// ---------------- normalize rows -> fp32 + bf16 ----------------
__global__ __launch_bounds__(256) void k_norm(const float* __restrict__ feats){
    int w = threadIdx.x >> 5, lane = threadIdx.x & 31;
    int row = blockIdx.x*8 + w;
    if (row >= NPG) return;
    float4 v = make_float4(0.f,0.f,0.f,0.f);
    if (row < NN){
        v = *(const float4*)(feats + (size_t)row*DD + lane*4);
        float ss = v.x*v.x + v.y*v.y + v.z*v.z + v.w*v.w;
        #pragma unroll
        for (int o=16;o;o>>=1) ss += __shfl_xor_sync(0xffffffffu, ss, o);
        float inv = 1.0f / fmaxf(sqrtf(ss), 1e-12f);
        v.x*=inv; v.y*=inv; v.z*=inv; v.w*=inv;
    }
    *(float4*)(g_xn + (size_t)row*DD + lane*4) = v;
    __nv_bfloat16 hi[4] = { __float2bfloat16_rn(v.x), __float2bfloat16_rn(v.y),
                            __float2bfloat16_rn(v.z), __float2bfloat16_rn(v.w) };
    *(uint2*)(g_xh + (size_t)row*DD + lane*4) = *(uint2*)hi;
}

// ---------------- approx sim = xh @ xh^T (symmetric, bf16 HMMA) ----------
#define LDSM4(r0,r1,r2,r3,addr) \
    asm volatile("ldmatrix.sync.aligned.m8n8.x4.shared.b16 {%0,%1,%2,%3},[%4];" \
        : "=r"(r0),"=r"(r1),"=r"(r2),"=r"(r3) : "r"(addr))
#define LDSM2(r0,r1,addr) \
    asm volatile("ldmatrix.sync.aligned.m8n8.x2.shared.b16 {%0,%1},[%2];" \
        : "=r"(r0),"=r"(r1) : "r"(addr))
#define MMA16816(c,a,b) \
    asm volatile("mma.sync.aligned.m16n8k16.row.col.f32.bf16.bf16.f32 " \
        "{%0,%1,%2,%3},{%4,%5,%6,%7},{%8,%9},{%0,%1,%2,%3};" \
        : "+f"(c[0]),"+f"(c[1]),"+f"(c[2]),"+f"(c[3]) \
        : "r"(a[0]),"r"(a[1]),"r"(a[2]),"r"(a[3]),"r"(b[0]),"r"(b[1]))

#define SROW2 136        // smem row stride in bf16 (272B) — conflict-free ldmatrix
#define SIM_SMEM (2*128*SROW2*2)   // 69632 bytes

__global__ __launch_bounds__(256) void k_simT(){
    extern __shared__ __align__(16) char smem[];
    char* sA = smem;
    char* sB = smem + 128*SROW2*2;

    const int bm = blockIdx.y, bn = blockIdx.x;
    if (bm > bn) return;                 // symmetric: upper triangle only

    const int tid  = threadIdx.x;
    const int wid  = tid >> 5;
    const int lane = tid & 31;
    const int warpM = (wid & 3) * 32;
    const int warpN = (wid >> 2) * 64;

    float c[2][8][4];
    #pragma unroll
    for (int t=0;t<2;t++)
        #pragma unroll
        for (int j=0;j<8;j++)
            #pragma unroll
            for (int q=0;q<4;q++) c[t][j][q] = 0.f;

    #pragma unroll
    for (int i=0;i<8;i++){
        int e = tid + i*256;
        int r = e >> 4, c8 = e & 15;
        size_t ga = (size_t)(bm*128 + r)*DD + c8*8;
        size_t gb = (size_t)(bn*128 + r)*DD + c8*8;
        *(uint4*)(sA + (r*SROW2 + c8*8)*2) = *(const uint4*)(g_xh + ga);
        *(uint4*)(sB + (r*SROW2 + c8*8)*2) = *(const uint4*)(g_xh + gb);
    }
    __syncthreads();

    uint32_t aoff = (uint32_t)((warpM + (lane & 15))*SROW2*2 + (lane >> 4)*16);
    uint32_t boff = (uint32_t)((warpN + (lane & 7))*SROW2*2 + ((lane >> 3) & 1)*16);
    uint32_t sA_u = (uint32_t)__cvta_generic_to_shared(sA);
    uint32_t sB_u = (uint32_t)__cvta_generic_to_shared(sB);

    #pragma unroll
    for (int ks=0; ks<8; ks++){
        uint32_t ah[2][4];
        #pragma unroll
        for (int t=0;t<2;t++){
            uint32_t ad = aoff + t*(16*SROW2*2) + ks*32;
            LDSM4(ah[t][0],ah[t][1],ah[t][2],ah[t][3], sA_u + ad);
        }
        #pragma unroll
        for (int j=0;j<8;j++){
            uint32_t bh[2];
            uint32_t bd = boff + j*(8*SROW2*2) + ks*32;
            LDSM2(bh[0],bh[1], sB_u + bd);
            #pragma unroll
            for (int t=0;t<2;t++)
                MMA16816(c[t][j], ah[t], bh);
        }
    }

    // direct write to (bm, bn)
    const int r0 = warpM + (lane >> 2);
    const int c0 = warpN + (lane & 3)*2;
    #pragma unroll
    for (int t=0;t<2;t++){
        #pragma unroll
        for (int j=0;j<8;j++){
            size_t base = (size_t)(bm*128 + r0 + t*16)*NPG + bn*128 + c0 + j*8;
            *(__nv_bfloat162*)(g_simh + base) =
                __float22bfloat162_rn(make_float2(c[t][j][0], c[t][j][1]));
            *(__nv_bfloat162*)(g_simh + base + 8ull*NPG) =
                __float22bfloat162_rn(make_float2(c[t][j][2], c[t][j][3]));
        }
    }

    // transposed write to (bn, bm) via smem staging (aliases sA/sB, dead now)
    if (bm != bn){
        __syncthreads();                       // all warps done reading sA/sB
        __nv_bfloat16* st = (__nv_bfloat16*)smem;   // [128 cols][SROW2] -> st[cl][rl]
        #pragma unroll
        for (int t=0;t<2;t++){
            #pragma unroll
            for (int j=0;j<8;j++){
                #pragma unroll
                for (int q=0;q<4;q++){
                    int rl = r0 + t*16 + (q>>1)*8;
                    int cl = c0 + j*8 + (q&1);
                    st[cl*SROW2 + rl] = __float2bfloat16_rn(c[t][j][q]);
                }
            }
        }
        __syncthreads();
        for (int e=tid; e<128*16; e+=256){
            int r = e >> 4, s8 = e & 15;
            uint4 v = *(uint4*)&st[r*SROW2 + s8*8];
            *(uint4*)(g_simh + (size_t)(bn*128 + r)*NPG + bm*128 + s8*8) = v;
        }
    }
}

// ---------------- per-row top-32 candidates (bf16 keys, u32 selection) -----
__device__ __forceinline__ uint32_t bf16key(uint32_t u16, int j){
    uint32_t m = (u16 & 0x8000u) ? ((~u16) & 0xFFFFu) : (u16 | 0x8000u);
    return (m << 14) | (uint32_t)(16383 - j);
}

__global__ __launch_bounds__(128) void k_topk(){
    __shared__ uint32_t sk[16][128];
    __shared__ uint32_t wmax[4];
    int row = blockIdx.x;
    int tid = threadIdx.x;
    const uint4* srow4 = (const uint4*)(g_simh + (size_t)row*NPG);

    uint32_t t[16];
    #pragma unroll
    for (int r=0;r<16;r++) t[r]=0u;

    #pragma unroll 1
    for (int it=0; it<10; it++){
        int v4 = it*128 + tid;
        if (v4 >= 1250) break;          // 1250*8 == 10000 exactly
        uint4 q = srow4[v4];
        int jb = v4*8;
        uint32_t ws[4] = {q.x, q.y, q.z, q.w};
        #pragma unroll
        for (int wv=0; wv<4; wv++){
            uint32_t klo = bf16key(ws[wv] & 0xFFFFu, jb + wv*2);
            uint32_t khi = bf16key(ws[wv] >> 16,     jb + wv*2 + 1);
            if (klo > t[15]){
                t[15] = klo;
                #pragma unroll
                for (int r=15;r>0;r--)
                    if (t[r] > t[r-1]){ uint32_t tmp=t[r-1]; t[r-1]=t[r]; t[r]=tmp; }
            }
            if (khi > t[15]){
                t[15] = khi;
                #pragma unroll
                for (int r=15;r>0;r--)
                    if (t[r] > t[r-1]){ uint32_t tmp=t[r-1]; t[r-1]=t[r]; t[r]=tmp; }
            }
        }
    }
    #pragma unroll
    for (int r=0;r<16;r++) sk[r][tid] = t[r];
    uint32_t lmax = t[0];               // t sorted desc
    __syncthreads();

    for (int sel=0; sel<NCAND; sel++){
        uint32_t m = lmax;
        #pragma unroll
        for (int o=16;o;o>>=1) m = kmax32(m, __shfl_xor_sync(0xffffffffu, m, o));
        if ((tid & 31) == 0) wmax[tid >> 5] = m;
        __syncthreads();
        uint32_t best = kmax32(kmax32(wmax[0],wmax[1]), kmax32(wmax[2],wmax[3]));
        if (lmax == best){
            #pragma unroll
            for (int r=0;r<16;r++){
                if (sk[r][tid] == best){ sk[r][tid] = 0u; break; }
            }
            uint32_t nm = 0u;
            #pragma unroll
            for (int r=0;r<16;r++) nm = kmax32(nm, sk[r][tid]);
            lmax = nm;
        }
        if (tid == 0) g_cand[(size_t)row*NCAND + sel] = 16383 - (int)(best & 16383u);
        __syncthreads();
    }
}

// ---------------- fp32 re-rank of 32 candidates -> top-16 ----------------
__global__ __launch_bounds__(256) void k_refine(){
    int w = threadIdx.x >> 5, lane = threadIdx.x & 31;
    int row = blockIdx.x*8 + w;
    if (row >= NN) return;
    float4 xr = *(const float4*)(g_xn + (size_t)row*DD + lane*4);
    int myidx = g_cand[(size_t)row*NCAND + lane];
    if ((unsigned)myidx >= (unsigned)NN) myidx = 0;
    unsigned long long mykey = 0ull;
    #pragma unroll 4
    for (int c=0; c<NCAND; c++){
        int cand = __shfl_sync(0xffffffffu, myidx, c);
        float4 xc = *(const float4*)(g_xn + (size_t)cand*DD + lane*4);
        float p = xr.x*xc.x + xr.y*xc.y + xr.z*xc.z + xr.w*xc.w;
        #pragma unroll
        for (int o=16;o;o>>=1) p += __shfl_xor_sync(0xffffffffu, p, o);
        if (lane == c){
            unsigned u = __float_as_uint(p);
            u = (u & 0x80000000u) ? ~u : (u | 0x80000000u);
            mykey = ((unsigned long long)u << 32) | (unsigned)(~(unsigned)myidx);
        }
    }
    int rank = 0;
    #pragma unroll
    for (int peer=0; peer<32; peer++){
        unsigned long long pk = __shfl_sync(0xffffffffu, mykey, peer);
        rank += (pk > mykey) ? 1 : 0;
    }
    if (rank < 16) g_knn[(size_t)row*16 + rank] = myidx;
}

// ---------------- mult logits: 4n x 4j register-tiled GEMM ----------------
// grid (40, K); block 256. n-tile 256, d-chunked (4 x 32d through smem).
#define XS_STRIDE 260
#define WT_STRIDE 20
template<int K>
__global__ __launch_bounds__(256) void k_mult(const float* __restrict__ feats,
                                              const int* __restrict__ idx,
                                              int stride, int off0,
                                              const float* __restrict__ wKK,
                                              const float* __restrict__ bKK,
                                              size_t moff){
    constexpr int NJC = K/16;
    __shared__ float xs[32*XS_STRIDE];          // [d in chunk][n], 33.3 KB
    __shared__ float wsT[NJC*32*WT_STRIDE];     // [jc][d][j]
    __shared__ int   sidx[256];

    const int tid = threadIdx.x;
    const int i  = blockIdx.y;
    const int n0 = blockIdx.x*256;
    const int tx = tid & 63;        // n-group: n = n0 + tx*4 + nn
    const int ty = tid >> 6;        // j-group: j = jc*16 + ty*4 + jj

    {
        int ng = n0 + tid;
        int s;
        if (idx == nullptr) s = (ng < NN) ? g_knn[(size_t)ng*16 + i] : 0;
        else                s = (ng < NN) ? idx[(size_t)ng*stride + off0 + i] : 0;
        if ((unsigned)s >= (unsigned)NN) s = 0;     // defensive clamp
        sidx[tid] = s;
    }

    float acc[NJC][4][4];
    #pragma unroll
    for (int jc=0;jc<NJC;jc++)
        #pragma unroll
        for (int a=0;a<4;a++)
            #pragma unroll
            for (int b=0;b<4;b++) acc[jc][a][b] = 0.f;

    #pragma unroll 1
    for (int chunk=0; chunk<4; chunk++){
        __syncthreads();
        // gather x chunk: 256 rows x 32 d, transposed into xs[d][n]
        #pragma unroll
        for (int p=0;p<8;p++){
            int e = tid + p*256;
            int row = e >> 3, d4 = e & 7;
            float4 v = *(const float4*)(feats + (size_t)sidx[row]*DD + chunk*32 + d4*4);
            xs[(d4*4+0)*XS_STRIDE + row] = v.x;
            xs[(d4*4+1)*XS_STRIDE + row] = v.y;
            xs[(d4*4+2)*XS_STRIDE + row] = v.z;
            xs[(d4*4+3)*XS_STRIDE + row] = v.w;
        }
        // weights chunk: wsT[jc][d][j]; per chunk each j-row contributes 8 float4
        for (int e=tid; e<NJC*128; e+=256){
            int jc = e >> 7;
            int j  = (e >> 3) & 15;
            int d4 = e & 7;
            float4 v = *(const float4*)(wKK + ((size_t)(i*K + jc*16 + j))*DD + chunk*32 + d4*4);
            wsT[jc*(32*WT_STRIDE) + (d4*4+0)*WT_STRIDE + j] = v.x;
            wsT[jc*(32*WT_STRIDE) + (d4*4+1)*WT_STRIDE + j] = v.y;
            wsT[jc*(32*WT_STRIDE) + (d4*4+2)*WT_STRIDE + j] = v.z;
            wsT[jc*(32*WT_STRIDE) + (d4*4+3)*WT_STRIDE + j] = v.w;
        }
        __syncthreads();

        #pragma unroll
        for (int d=0; d<32; d++){
            float4 xv = *(float4*)&xs[d*XS_STRIDE + tx*4];
            #pragma unroll
            for (int jc=0; jc<NJC; jc++){
                float4 wv = *(float4*)&wsT[jc*(32*WT_STRIDE) + d*WT_STRIDE + ty*4];
                acc[jc][0][0] += xv.x*wv.x; acc[jc][0][1] += xv.x*wv.y;
                acc[jc][0][2] += xv.x*wv.z; acc[jc][0][3] += xv.x*wv.w;
                acc[jc][1][0] += xv.y*wv.x; acc[jc][1][1] += xv.y*wv.y;
                acc[jc][1][2] += xv.y*wv.z; acc[jc][1][3] += xv.y*wv.w;
                acc[jc][2][0] += xv.z*wv.x; acc[jc][2][1] += xv.z*wv.y;
                acc[jc][2][2] += xv.z*wv.z; acc[jc][2][3] += xv.z*wv.w;
                acc[jc][3][0] += xv.w*wv.x; acc[jc][3][1] += xv.w*wv.y;
                acc[jc][3][2] += xv.w*wv.z; acc[jc][3][3] += xv.w*wv.w;
            }
        }
    }

    if (n0 + tx*4 < NP){
        #pragma unroll
        for (int jc=0; jc<NJC; jc++){
            #pragma unroll
            for (int jj=0; jj<4; jj++){
                int jglob = jc*16 + ty*4 + jj;
                float b = __ldg(&bKK[i*K + jglob]);
                *(float4*)(g_mult + moff + (size_t)(i*K + jglob)*NP + n0 + tx*4) =
                    make_float4(acc[jc][0][jj]+b, acc[jc][1][jj]+b,
                                acc[jc][2][jj]+b, acc[jc][3][jj]+b);
            }
        }
    }
}

// ---------------- coef[j][n] = sum_i wK1[i]*softmax_j(mult[i][:,n]) ---------
template<int K>
__device__ __forceinline__ void coef_body(int n, size_t moff, size_t coff,
                                          const float* __restrict__ wK1){
    const float* mout = g_mult + moff;
    float cacc[K];
    #pragma unroll
    for (int j=0;j<K;j++) cacc[j]=0.f;
    #pragma unroll
    for (int i=0;i<K;i++){
        float v[K];
        float m = -1e30f;
        #pragma unroll
        for (int j=0;j<K;j++){
            v[j] = mout[((size_t)(i*K + j))*NP + n];
            m = fmaxf(m, v[j]);
        }
        float s = 0.f;
        #pragma unroll
        for (int j=0;j<K;j++){ v[j] = __expf(v[j]-m); s += v[j]; }
        float w = wK1[i] / s;
        #pragma unroll
        for (int j=0;j<K;j++) cacc[j] += w * v[j];
    }
    float* cout = g_coef + coff;
    #pragma unroll
    for (int j=0;j<K;j++) cout[(size_t)j*NP + n] = cacc[j];
}

// mode 0: blockIdx.y in {0,1,2,3} -> branches {0,1,2,4} (side chain)
// mode 1: branch 3 (knn) only
__global__ __launch_bounds__(256) void k_coef_all(const float* __restrict__ wK1_c,
                                                  const float* __restrict__ wK1_n,
                                                  const float* __restrict__ wK1_s,
                                                  int mode){
    int n = blockIdx.x*256 + threadIdx.x;
    if (n >= NN) return;
    const size_t M16 = (size_t)256*NP;
    int br = (mode == 1) ? 3 : ((blockIdx.y == 3) ? 4 : blockIdx.y);
    if (br < 3)       coef_body<16>(n, (size_t)br*M16, (size_t)br*16*NP, wK1_c);
    else if (br == 3) coef_body<16>(n, 3*M16, (size_t)48*NP, wK1_n);
    else              coef_body<32>(n, 4*M16, (size_t)64*NP, wK1_s);
}

// ---------------- hyper[n][t][:] = sum_j coef[j][n]*feats[idx(n,j)] + bK1 ---
__global__ __launch_bounds__(256) void k_hyper_all(const float* __restrict__ feats,
                                                   const int* __restrict__ cidx,
                                                   const int* __restrict__ sidx,
                                                   const float* __restrict__ bK1_c,
                                                   const float* __restrict__ bK1_n,
                                                   const float* __restrict__ bK1_s,
                                                   int mode){
    int w = threadIdx.x >> 5, lane = threadIdx.x & 31;
    int n = blockIdx.x*8 + w;
    if (n >= NN) return;
    int t = (mode == 1) ? 3 : ((blockIdx.y == 3) ? 4 : blockIdx.y);
    const int* idx; int stride, off0, K; const float* bK1; size_t coff;
    if (t < 3){ idx = cidx; stride = 48; off0 = t*16; K = 16; bK1 = bK1_c; coff = (size_t)t*16*NP; }
    else if (t == 3){ idx = g_knn; stride = 16; off0 = 0; K = 16; bK1 = bK1_n; coff = (size_t)48*NP; }
    else { idx = sidx; stride = 32; off0 = 0; K = 32; bK1 = bK1_s; coff = (size_t)64*NP; }

    const float* coef = g_coef + coff;
    float4 acc = make_float4(0.f,0.f,0.f,0.f);
    #pragma unroll 4
    for (int j=0;j<K;j++){
        float c = __ldg(&coef[(size_t)j*NP + n]);
        int src = idx[(size_t)n*stride + off0 + j];
        if ((unsigned)src >= (unsigned)NN) src = 0;
        float4 f = *(const float4*)(feats + (size_t)src*DD + lane*4);
        acc.x += c*f.x; acc.y += c*f.y; acc.z += c*f.z; acc.w += c*f.w;
    }
    float b = bK1[0];
    acc.x += b; acc.y += b; acc.z += b; acc.w += b;
    *(float4*)(g_hyper + ((size_t)n*5 + t)*DD + lane*4) = acc;
}

// ---------------- EdgeConv attention + final FC ----------------
__global__ __launch_bounds__(128) void k_final(const float* __restrict__ ec_w1,
                                               const float* __restrict__ ec_b1,
                                               const float* __restrict__ ec_w2,
                                               const float* __restrict__ ec_b2,
                                               const float* __restrict__ fc_w,
                                               const float* __restrict__ fc_b,
                                               float* __restrict__ out){
    extern __shared__ float fsm[];
    float* fcw  = fsm;
    float* w1s  = fsm + 16384;
    float* xs   = fsm + 16384 + 4096;
    float* aggs = xs + 4*640;
    int tid = threadIdx.x;
    for (int e=tid; e<16384/4; e+=128)
        *(float4*)&fcw[e*4] = *(const float4*)&fc_w[e*4];
    for (int e=tid; e<4096/4; e+=128)
        *(float4*)&w1s[e*4] = *(const float4*)&ec_w1[e*4];
    __syncthreads();

    int w = tid >> 5, lane = tid & 31;
    int n = blockIdx.x*4 + w;

    float4 xr[5];
    #pragma unroll
    for (int t=0;t<5;t++){
        xr[t] = *(const float4*)(g_hyper + ((size_t)n*5 + t)*DD + lane*4);
        *(float4*)&xs[w*640 + t*128 + lane*4] = xr[t];
    }
    __syncwarp();

    float w2v = ec_w2[lane];
    float b1v = ec_b1[lane];
    float sc[5];
    #pragma unroll
    for (int t=0;t<5;t++){
        float h = b1v;
        #pragma unroll 4
        for (int d=0; d<DD; d++)
            h += xs[w*640 + t*128 + d] * w1s[d*32 + lane];
        h = fmaxf(h, 0.f);
        float p = h * w2v;
        #pragma unroll
        for (int o=16;o;o>>=1) p += __shfl_xor_sync(0xffffffffu, p, o);
        sc[t] = p;
    }
    float b2 = ec_b2[0];
    float m = -1e30f;
    #pragma unroll
    for (int t=0;t<5;t++){ sc[t] += b2; m = fmaxf(m, sc[t]); }
    float s = 0.f;
    #pragma unroll
    for (int t=0;t<5;t++){ sc[t] = __expf(sc[t]-m); s += sc[t]; }
    float inv = 1.f/s;
    #pragma unroll
    for (int t=0;t<5;t++) sc[t] *= inv;

    float4 a = make_float4(0.f,0.f,0.f,0.f);
    #pragma unroll
    for (int t=0;t<5;t++){
        a.x += sc[t]*xr[t].x; a.y += sc[t]*xr[t].y;
        a.z += sc[t]*xr[t].z; a.w += sc[t]*xr[t].w;
    }
    *(float4*)&aggs[w*128 + lane*4] = a;
    __syncwarp();

    float4 o = *(const float4*)&fc_b[lane*4];
    #pragma unroll 4
    for (int d=0; d<DD; d++){
        float av = aggs[w*128 + d];
        float4 fw = *(const float4*)&fcw[d*128 + lane*4];
        o.x += av*fw.x; o.y += av*fw.y; o.z += av*fw.z; o.w += av*fw.w;
    }
    o.x = fmaxf(o.x,0.f); o.y = fmaxf(o.y,0.f);
    o.z = fmaxf(o.z,0.f); o.w = fmaxf(o.w,0.f);
    *(float4*)(out + (size_t)n*DD + lane*4) = o;
}

// ---------------- launch ----------------
static cudaStream_t g_s2 = nullptr;
static cudaEvent_t  g_evF = nullptr, g_evJ = nullptr;

extern "C" void kernel_launch(void* const* d_in, const int* in_sizes, int n_in,
                              void* d_out, int out_size){
    const float* feats  = (const float*)d_in[1];
    const int*   cidx   = (const int*)d_in[2];
    const int*   sidx   = (const int*)d_in[3];
    const float* wKK_c  = (const float*)d_in[5];
    const float* bKK_c  = (const float*)d_in[6];
    const float* wK1_c  = (const float*)d_in[7];
    const float* bK1_c  = (const float*)d_in[8];
    const float* wKK_n  = (const float*)d_in[9];
    const float* bKK_n  = (const float*)d_in[10];
    const float* wK1_n  = (const float*)d_in[11];
    const float* bK1_n  = (const float*)d_in[12];
    const float* wKK_s  = (const float*)d_in[13];
    const float* bKK_s  = (const float*)d_in[14];
    const float* wK1_s  = (const float*)d_in[15];
    const float* bK1_s  = (const float*)d_in[16];
    const float* ec_w1  = (const float*)d_in[17];
    const float* ec_b1  = (const float*)d_in[18];
    const float* ec_w2  = (const float*)d_in[19];
    const float* ec_b2  = (const float*)d_in[20];
    const float* fc_w   = (const float*)d_in[21];
    const float* fc_b   = (const float*)d_in[22];
    float* out = (float*)d_out;

    if (g_s2 == nullptr){
        cudaStreamCreateWithFlags(&g_s2, cudaStreamNonBlocking);
        cudaEventCreateWithFlags(&g_evF, cudaEventDisableTiming);
        cudaEventCreateWithFlags(&g_evJ, cudaEventDisableTiming);
    }

    cudaFuncSetAttribute(k_simT, cudaFuncAttributeMaxDynamicSharedMemorySize, SIM_SMEM);
    cudaFuncSetAttribute(k_final, cudaFuncAttributeMaxDynamicSharedMemorySize, 94208);

    const size_t M16 = (size_t)256*NP;
    int cb = (NN + 255)/256;

    // fork side chain (cluster + struct branches; independent of knn)
    cudaEventRecord(g_evF, 0);
    cudaStreamWaitEvent(g_s2, g_evF, 0);

    // side chain on g_s2
    for (int c=0;c<3;c++)
        k_mult<16><<<dim3(40,16),256,0,g_s2>>>(feats, cidx, 48, c*16, wKK_c, bKK_c, (size_t)c*M16);
    k_mult<32><<<dim3(40,32),256,0,g_s2>>>(feats, sidx, 32, 0, wKK_s, bKK_s, 4*M16);
    k_coef_all<<<dim3(cb,4),256,0,g_s2>>>(wK1_c, wK1_n, wK1_s, 0);
    k_hyper_all<<<dim3(NN/8,4),256,0,g_s2>>>(feats, cidx, sidx, bK1_c, bK1_n, bK1_s, 0);
    cudaEventRecord(g_evJ, g_s2);

    // main chain on default stream (knn pipeline)
    k_norm<<<NPG/8, 256>>>(feats);
    k_simT<<<dim3(NPG/128, NPG/128), 256, SIM_SMEM>>>();
    k_topk<<<NN, 128>>>();
    k_refine<<<(NN+7)/8, 256>>>();
    k_mult<16><<<dim3(40,16),256>>>(feats, nullptr, 16, 0, wKK_n, bKK_n, 3*M16);
    k_coef_all<<<dim3(cb,1),256>>>(wK1_c, wK1_n, wK1_s, 1);
    k_hyper_all<<<dim3(NN/8,1),256>>>(feats, cidx, sidx, bK1_c, bK1_n, bK1_s, 1);

    // join, then final
    cudaStreamWaitEvent(0, g_evJ, 0);
    k_final<<<NN/4, 128, 94208>>>(ec_w1, ec_b1, ec_w2, ec_b2, fc_w, fc_b, out);
}